// round 2
// baseline (speedup 1.0000x reference)
#include <cuda_runtime.h>
#include <cuda_bf16.h>
#include <math.h>

// ---------------------------------------------------------------------------
// GroupedQueryAttention: X@Wq/Wk/Wv -> RoPE -> GQA flash attention -> @Wo
// b=2, s=2048, HIDDEN=4096, 32 q-heads, 8 kv-heads, d=128, full (non-causal)
// Round 2: fp32 SIMT baseline + position_ids dtype auto-detection (int64 vs
// int32 materialization by the harness).
// ---------------------------------------------------------------------------

#define B_ 2
#define S_ 2048
#define HID 4096
#define NH 32
#define NKV 8
#define HD 128
#define TOKENS (B_ * S_)

// Static device scratch (no cudaMalloc allowed)
__device__ float g_Q[TOKENS * NH * HD];   // 64 MB
__device__ float g_K[TOKENS * NKV * HD];  // 16 MB
__device__ float g_V[TOKENS * NKV * HD];  // 16 MB
__device__ float g_A[TOKENS * NH * HD];   // 64 MB
__device__ int   g_pos_is64;

// ===========================================================================
// position_ids dtype detection.
// If the buffer holds little-endian int64 values (all < 2^31 here), the
// int32 view has zero high-words at odd indices. If it holds int32 arange
// positions, indices 1,3,5,7 are 1,3,5,7 (nonzero).
// ===========================================================================
__global__ void detect_pos_kernel(const int* __restrict__ p)
{
    if (threadIdx.x == 0 && blockIdx.x == 0) {
        g_pos_is64 = (p[1] == 0 && p[3] == 0 && p[5] == 0 && p[7] == 0) ? 1 : 0;
    }
}

// ===========================================================================
// SGEMM: C[M,N] = A[M,K] @ B[K,N], row-major, M,N multiples of 128, K mult of 8
// 128x128 block tile, 8x8 per thread, BK=8, 256 threads.
// ===========================================================================
__global__ __launch_bounds__(256) void sgemm_kernel(
    const float* __restrict__ A, const float* __restrict__ B,
    float* __restrict__ C, int M, int N, int K)
{
    __shared__ float As[8][128];  // transposed A tile
    __shared__ float Bs[8][128];

    const int bx = blockIdx.x;   // N tile
    const int by = blockIdx.y;   // M tile
    const int tid = threadIdx.x;

    const int aRow = tid >> 1;            // 0..127
    const int aCol = (tid & 1) << 2;      // 0 or 4
    const int bRow = tid >> 5;            // 0..7
    const int bCol = (tid & 31) << 2;     // 0..124

    const int tr = tid >> 4;              // 0..15
    const int tc = tid & 15;              // 0..15

    const float* Ablk = A + (size_t)by * 128 * K;
    const float* Bblk = B + (size_t)bx * 128;

    float acc[8][8];
    #pragma unroll
    for (int i = 0; i < 8; i++)
        #pragma unroll
        for (int j = 0; j < 8; j++) acc[i][j] = 0.f;

    for (int k0 = 0; k0 < K; k0 += 8) {
        float4 av = *(const float4*)(Ablk + (size_t)aRow * K + k0 + aCol);
        As[aCol + 0][aRow] = av.x;
        As[aCol + 1][aRow] = av.y;
        As[aCol + 2][aRow] = av.z;
        As[aCol + 3][aRow] = av.w;
        float4 bv = *(const float4*)(Bblk + (size_t)(k0 + bRow) * N + bCol);
        *(float4*)(&Bs[bRow][bCol]) = bv;
        __syncthreads();

        #pragma unroll
        for (int k = 0; k < 8; k++) {
            float4 a0 = *(const float4*)(&As[k][tr * 8]);
            float4 a1 = *(const float4*)(&As[k][tr * 8 + 4]);
            float4 b0 = *(const float4*)(&Bs[k][tc * 8]);
            float4 b1 = *(const float4*)(&Bs[k][tc * 8 + 4]);
            float ra[8] = {a0.x, a0.y, a0.z, a0.w, a1.x, a1.y, a1.z, a1.w};
            float rb[8] = {b0.x, b0.y, b0.z, b0.w, b1.x, b1.y, b1.z, b1.w};
            #pragma unroll
            for (int i = 0; i < 8; i++)
                #pragma unroll
                for (int j = 0; j < 8; j++)
                    acc[i][j] = fmaf(ra[i], rb[j], acc[i][j]);
        }
        __syncthreads();
    }

    float* Cblk = C + (size_t)by * 128 * N + (size_t)bx * 128;
    #pragma unroll
    for (int i = 0; i < 8; i++) {
        float4 c0 = make_float4(acc[i][0], acc[i][1], acc[i][2], acc[i][3]);
        float4 c1 = make_float4(acc[i][4], acc[i][5], acc[i][6], acc[i][7]);
        *(float4*)(&Cblk[(size_t)(tr * 8 + i) * N + tc * 8])     = c0;
        *(float4*)(&Cblk[(size_t)(tr * 8 + i) * N + tc * 8 + 4]) = c1;
    }
}

// ===========================================================================
// RoPE: in-place on Q [tok, 32, 128] and K [tok, 8, 128]
// Reads position via int32 view; g_pos_is64 selects stride (2*token for
// little-endian int64 data, token for int32 data).
// ===========================================================================
__global__ __launch_bounds__(256) void rope_kernel(
    float* __restrict__ Q, float* __restrict__ K,
    const int* __restrict__ pos32)
{
    const int token = blockIdx.x;
    const int pidx = g_pos_is64 ? (token << 1) : token;
    const float p = (float)pos32[pidx];
    const int tid = threadIdx.x;

    float* Qb = Q + (size_t)token * (NH * HD);
    for (int idx = tid; idx < NH * 64; idx += 256) {
        int h = idx >> 6, i = idx & 63;
        float inv = powf(10000.0f, -(float)(2 * i) * (1.0f / 128.0f));
        float sv, cv;
        sincosf(p * inv, &sv, &cv);
        float x1 = Qb[h * HD + i];
        float x2 = Qb[h * HD + i + 64];
        Qb[h * HD + i]      = x1 * cv - x2 * sv;
        Qb[h * HD + i + 64] = x2 * cv + x1 * sv;
    }

    float* Kb = K + (size_t)token * (NKV * HD);
    for (int idx = tid; idx < NKV * 64; idx += 256) {
        int h = idx >> 6, i = idx & 63;
        float inv = powf(10000.0f, -(float)(2 * i) * (1.0f / 128.0f));
        float sv, cv;
        sincosf(p * inv, &sv, &cv);
        float x1 = Kb[h * HD + i];
        float x2 = Kb[h * HD + i + 64];
        Kb[h * HD + i]      = x1 * cv - x2 * sv;
        Kb[h * HD + i + 64] = x2 * cv + x1 * sv;
    }
}

// ===========================================================================
// Flash attention (non-causal): 64 q-rows per block, 64-key tiles, d=128.
// 256 threads. Dynamic smem: Qs[64][132] + KVs[64][132] + Ps[64][68] + stats.
// ===========================================================================
#define QS 132
#define PS 68
#define ATT_SMEM_FLOATS (64 * QS * 2 + 64 * PS + 192)
#define ATT_SMEM_BYTES (ATT_SMEM_FLOATS * 4)

__global__ __launch_bounds__(256) void attn_kernel(
    const float* __restrict__ Q, const float* __restrict__ K,
    const float* __restrict__ V, float* __restrict__ O)
{
    extern __shared__ float sm[];
    float* Qs  = sm;                   // 64 * 132
    float* KVs = Qs + 64 * QS;         // 64 * 132
    float* Ps  = KVs + 64 * QS;        // 64 * 68
    float* m_s  = Ps + 64 * PS;        // 64
    float* l_s  = m_s + 64;            // 64
    float* sc_s = l_s + 64;            // 64

    const int qt = blockIdx.x;         // q tile (0..31)
    const int h  = blockIdx.y;         // q head (0..31)
    const int b  = blockIdx.z;         // batch
    const int kvh = h >> 2;            // GROUPS = 4

    const int tid = threadIdx.x;
    const int tq = tid >> 4;           // 0..15 -> owns q rows tq*4..tq*4+3
    const int tx = tid & 15;           // 0..15
    const int w = tid >> 5, lane = tid & 31;

    const float scale = 0.08838834764831845f;  // 1/sqrt(128)

    // Load Q tile
    const float* Qg = Q + (((size_t)b * S_ + (size_t)qt * 64) * NH + h) * HD;
    for (int i = tid; i < 64 * 32; i += 256) {
        int r = i >> 5, c4 = (i & 31) << 2;
        *(float4*)(Qs + r * QS + c4) =
            *(const float4*)(Qg + (size_t)r * (NH * HD) + c4);
    }
    if (tid < 64) { m_s[tid] = -INFINITY; l_s[tid] = 0.f; }

    float o_acc[4][8];
    #pragma unroll
    for (int i = 0; i < 4; i++)
        #pragma unroll
        for (int j = 0; j < 8; j++) o_acc[i][j] = 0.f;

    const float* Kg = K + ((size_t)b * S_ * NKV + kvh) * HD;
    const float* Vg = V + ((size_t)b * S_ * NKV + kvh) * HD;
    const size_t kvstride = (size_t)NKV * HD;  // 1024

    for (int kt = 0; kt < S_ / 64; kt++) {
        __syncthreads();  // protects KVs (read in prev PV) and Ps
        // Load K tile
        for (int i = tid; i < 64 * 32; i += 256) {
            int r = i >> 5, c4 = (i & 31) << 2;
            *(float4*)(KVs + r * QS + c4) =
                *(const float4*)(Kg + (size_t)(kt * 64 + r) * kvstride + c4);
        }
        __syncthreads();

        // S = Q K^T  (each thread: 4 q-rows x 4 k-cols, cols tx + 16*j)
        float s_acc[4][4];
        #pragma unroll
        for (int i = 0; i < 4; i++)
            #pragma unroll
            for (int j = 0; j < 4; j++) s_acc[i][j] = 0.f;

        for (int d = 0; d < HD; d += 4) {
            float4 qa[4], kb[4];
            #pragma unroll
            for (int i = 0; i < 4; i++)
                qa[i] = *(const float4*)(&Qs[(tq * 4 + i) * QS + d]);
            #pragma unroll
            for (int j = 0; j < 4; j++)
                kb[j] = *(const float4*)(&KVs[(tx + 16 * j) * QS + d]);
            #pragma unroll
            for (int i = 0; i < 4; i++)
                #pragma unroll
                for (int j = 0; j < 4; j++) {
                    s_acc[i][j] = fmaf(qa[i].x, kb[j].x, s_acc[i][j]);
                    s_acc[i][j] = fmaf(qa[i].y, kb[j].y, s_acc[i][j]);
                    s_acc[i][j] = fmaf(qa[i].z, kb[j].z, s_acc[i][j]);
                    s_acc[i][j] = fmaf(qa[i].w, kb[j].w, s_acc[i][j]);
                }
        }
        #pragma unroll
        for (int i = 0; i < 4; i++)
            #pragma unroll
            for (int j = 0; j < 4; j++)
                Ps[(tq * 4 + i) * PS + tx + 16 * j] = s_acc[i][j] * scale;
        __syncthreads();

        // Online softmax: warp w handles rows w*8..w*8+7
        for (int rr = 0; rr < 8; rr++) {
            int r = w * 8 + rr;
            float v0 = Ps[r * PS + lane];
            float v1 = Ps[r * PS + lane + 32];
            float mx = fmaxf(v0, v1);
            #pragma unroll
            for (int off = 16; off > 0; off >>= 1)
                mx = fmaxf(mx, __shfl_xor_sync(0xffffffffu, mx, off));
            float m_old = m_s[r];
            float m_new = fmaxf(m_old, mx);
            float p0 = __expf(v0 - m_new);
            float p1 = __expf(v1 - m_new);
            Ps[r * PS + lane]      = p0;
            Ps[r * PS + lane + 32] = p1;
            float sm2 = p0 + p1;
            #pragma unroll
            for (int off = 16; off > 0; off >>= 1)
                sm2 += __shfl_xor_sync(0xffffffffu, sm2, off);
            if (lane == 0) {
                float scf = __expf(m_old - m_new);
                sc_s[r] = scf;
                l_s[r] = l_s[r] * scf + sm2;
                m_s[r] = m_new;
            }
        }
        __syncthreads();

        // Rescale O and load V tile (independent)
        float rs[4];
        #pragma unroll
        for (int i = 0; i < 4; i++) rs[i] = sc_s[tq * 4 + i];
        #pragma unroll
        for (int i = 0; i < 4; i++)
            #pragma unroll
            for (int j = 0; j < 8; j++) o_acc[i][j] *= rs[i];

        for (int i = tid; i < 64 * 32; i += 256) {
            int r = i >> 5, c4 = (i & 31) << 2;
            *(float4*)(KVs + r * QS + c4) =
                *(const float4*)(Vg + (size_t)(kt * 64 + r) * kvstride + c4);
        }
        __syncthreads();

        // O += P @ V  (thread: 4 q-rows x 8 d-cols, cols tx + 16*j)
        for (int k = 0; k < 64; k += 4) {
            float4 pa[4];
            #pragma unroll
            for (int i = 0; i < 4; i++)
                pa[i] = *(const float4*)(&Ps[(tq * 4 + i) * PS + k]);
            #pragma unroll
            for (int kk = 0; kk < 4; kk++) {
                float pv[8];
                #pragma unroll
                for (int j = 0; j < 8; j++)
                    pv[j] = KVs[(k + kk) * QS + tx + 16 * j];
                float pav[4] = {
                    kk == 0 ? pa[0].x : kk == 1 ? pa[0].y : kk == 2 ? pa[0].z : pa[0].w,
                    kk == 0 ? pa[1].x : kk == 1 ? pa[1].y : kk == 2 ? pa[1].z : pa[1].w,
                    kk == 0 ? pa[2].x : kk == 1 ? pa[2].y : kk == 2 ? pa[2].z : pa[2].w,
                    kk == 0 ? pa[3].x : kk == 1 ? pa[3].y : kk == 2 ? pa[3].z : pa[3].w
                };
                #pragma unroll
                for (int i = 0; i < 4; i++)
                    #pragma unroll
                    for (int j = 0; j < 8; j++)
                        o_acc[i][j] = fmaf(pav[i], pv[j], o_acc[i][j]);
            }
        }
    }
    __syncthreads();

    // Write out / l
    float* Og = O + (((size_t)b * S_ + (size_t)qt * 64) * NH + h) * HD;
    #pragma unroll
    for (int i = 0; i < 4; i++) {
        float inv_l = 1.0f / l_s[tq * 4 + i];
        #pragma unroll
        for (int j = 0; j < 8; j++)
            Og[(size_t)(tq * 4 + i) * (NH * HD) + tx + 16 * j] =
                o_acc[i][j] * inv_l;
    }
}

// ===========================================================================
// Launch
// ===========================================================================
extern "C" void kernel_launch(void* const* d_in, const int* in_sizes, int n_in,
                              void* d_out, int out_size)
{
    const float* X       = (const float*)d_in[0];
    const int*   pos32   = (const int*)d_in[1];
    const float* Wq = (const float*)d_in[2];
    const float* Wk = (const float*)d_in[3];
    const float* Wv = (const float*)d_in[4];
    const float* Wo = (const float*)d_in[5];
    float* out = (float*)d_out;

    float *Qp, *Kp, *Vp, *Ap;
    cudaGetSymbolAddress((void**)&Qp, g_Q);
    cudaGetSymbolAddress((void**)&Kp, g_K);
    cudaGetSymbolAddress((void**)&Vp, g_V);
    cudaGetSymbolAddress((void**)&Ap, g_A);

    cudaFuncSetAttribute(attn_kernel,
                         cudaFuncAttributeMaxDynamicSharedMemorySize,
                         ATT_SMEM_BYTES);

    dim3 blk(256);
    // position dtype probe
    detect_pos_kernel<<<1, 1>>>(pos32);
    // Q/K/V projections
    sgemm_kernel<<<dim3(HID / 128, TOKENS / 128), blk>>>(X, Wq, Qp, TOKENS, HID, HID);
    sgemm_kernel<<<dim3((NKV * HD) / 128, TOKENS / 128), blk>>>(X, Wk, Kp, TOKENS, NKV * HD, HID);
    sgemm_kernel<<<dim3((NKV * HD) / 128, TOKENS / 128), blk>>>(X, Wv, Vp, TOKENS, NKV * HD, HID);
    // RoPE
    rope_kernel<<<TOKENS, 256>>>(Qp, Kp, pos32);
    // Attention
    attn_kernel<<<dim3(S_ / 64, NH, B_), 256, ATT_SMEM_BYTES>>>(Qp, Kp, Vp, Ap);
    // Output projection
    sgemm_kernel<<<dim3(HID / 128, TOKENS / 128), blk>>>(Ap, Wo, out, TOKENS, HID, HID);
}

// round 4
// speedup vs baseline: 1.8585x; 1.8585x over previous
#include <cuda_runtime.h>
#include <cuda_bf16.h>
#include <math.h>
#include <stdint.h>

// ---------------------------------------------------------------------------
// GroupedQueryAttention on GB300 (sm_103a die, but harness PTX target is
// compute_103 WITHOUT the 'a' feature set -> no tcgen05/TMEM. Tensor path:
// warp-level mma.sync bf16 (split-precision, fp32 accumulate) + ldmatrix +
// cp.async double buffering.
// Round 4: all 4 GEMMs on mma.sync; attention stays SIMT fp32.
// ---------------------------------------------------------------------------

#define B_ 2
#define S_ 2048
#define HID 4096
#define NH 32
#define NKV 8
#define HD 128
#define TOKENS (B_ * S_)
#define KVDIM (NKV * HD)   // 1024

// fp32 activation scratch
__device__ float g_Q[TOKENS * NH * HD];
__device__ float g_K[TOKENS * NKV * HD];
__device__ float g_V[TOKENS * NKV * HD];
__device__ float g_A[TOKENS * NH * HD];
__device__ int   g_pos_is64;

// bf16 split scratch
__device__ __nv_bfloat16 g_Xh[TOKENS * HID];
__device__ __nv_bfloat16 g_Xl[TOKENS * HID];
__device__ __nv_bfloat16 g_Ah[TOKENS * HID];
__device__ __nv_bfloat16 g_Al[TOKENS * HID];
__device__ __nv_bfloat16 g_Wqh[HID * HID];
__device__ __nv_bfloat16 g_Wql[HID * HID];
__device__ __nv_bfloat16 g_Wkh[KVDIM * HID];
__device__ __nv_bfloat16 g_Wkl[KVDIM * HID];
__device__ __nv_bfloat16 g_Wvh[KVDIM * HID];
__device__ __nv_bfloat16 g_Wvl[KVDIM * HID];
__device__ __nv_bfloat16 g_Woh[HID * HID];
__device__ __nv_bfloat16 g_Wol[HID * HID];

// ===========================================================================
// Helpers
// ===========================================================================
__device__ __forceinline__ uint32_t smem_u32(const void* p) {
    uint32_t a;
    asm("{ .reg .u64 t; cvta.to.shared.u64 t, %1; cvt.u32.u64 %0, t; }"
        : "=r"(a) : "l"(p));
    return a;
}
__device__ __forceinline__ uint32_t swz(uint32_t off) {
    return off ^ ((off >> 3) & 0x70);
}

#define CP_ASYNC16(dst, src) \
    asm volatile("cp.async.cg.shared.global [%0], [%1], 16;" \
        :: "r"(dst), "l"(src) : "memory")
#define CP_COMMIT() asm volatile("cp.async.commit_group;" ::: "memory")
#define CP_WAIT(n)  asm volatile("cp.async.wait_group %0;" :: "n"(n) : "memory")

#define LDSM_X4(r0, r1, r2, r3, addr) \
    asm volatile("ldmatrix.sync.aligned.m8n8.x4.shared.b16 {%0,%1,%2,%3}, [%4];" \
        : "=r"(r0), "=r"(r1), "=r"(r2), "=r"(r3) : "r"(addr))

#define MMA_BF16(d, a, b0v, b1v) \
    asm volatile("mma.sync.aligned.m16n8k16.row.col.f32.bf16.bf16.f32 " \
        "{%0,%1,%2,%3}, {%4,%5,%6,%7}, {%8,%9}, {%0,%1,%2,%3};" \
        : "+f"((d)[0]), "+f"((d)[1]), "+f"((d)[2]), "+f"((d)[3]) \
        : "r"((a)[0]), "r"((a)[1]), "r"((a)[2]), "r"((a)[3]), \
          "r"(b0v), "r"(b1v))

// ===========================================================================
// position_ids dtype probe (int64 little-endian => zero high words)
// ===========================================================================
__global__ void detect_pos_kernel(const int* __restrict__ p)
{
    if (threadIdx.x == 0 && blockIdx.x == 0)
        g_pos_is64 = (p[1] == 0 && p[3] == 0 && p[5] == 0 && p[7] == 0) ? 1 : 0;
}

// ===========================================================================
// Split fp32 -> (bf16 hi, bf16 lo)
// ===========================================================================
__global__ __launch_bounds__(256) void split_kernel(
    const float* __restrict__ x, __nv_bfloat16* __restrict__ h,
    __nv_bfloat16* __restrict__ l, int n4)
{
    int i = blockIdx.x * 256 + threadIdx.x;
    if (i >= n4) return;
    float4 v = *(const float4*)(x + (size_t)i * 4);
    __nv_bfloat16 h0 = __float2bfloat16_rn(v.x);
    __nv_bfloat16 h1 = __float2bfloat16_rn(v.y);
    __nv_bfloat16 h2 = __float2bfloat16_rn(v.z);
    __nv_bfloat16 h3 = __float2bfloat16_rn(v.w);
    __nv_bfloat16 l0 = __float2bfloat16_rn(v.x - __bfloat162float(h0));
    __nv_bfloat16 l1 = __float2bfloat16_rn(v.y - __bfloat162float(h1));
    __nv_bfloat16 l2 = __float2bfloat16_rn(v.z - __bfloat162float(h2));
    __nv_bfloat16 l3 = __float2bfloat16_rn(v.w - __bfloat162float(h3));
    __nv_bfloat162* H = (__nv_bfloat162*)(h + (size_t)i * 4);
    __nv_bfloat162* L = (__nv_bfloat162*)(l + (size_t)i * 4);
    H[0] = __nv_bfloat162(h0, h1); H[1] = __nv_bfloat162(h2, h3);
    L[0] = __nv_bfloat162(l0, l1); L[1] = __nv_bfloat162(l2, l3);
}

// ===========================================================================
// Transpose + split: W [Kd, Nd] fp32 -> Th/Tl [Nd, Kd] bf16
// ===========================================================================
__global__ __launch_bounds__(256) void transpose_split_kernel(
    const float* __restrict__ W, __nv_bfloat16* __restrict__ Th,
    __nv_bfloat16* __restrict__ Tl, int Kd, int Nd)
{
    __shared__ float t[32][33];
    const int n0 = blockIdx.x * 32, k0 = blockIdx.y * 32;
    const int tx = threadIdx.x & 31, ty = threadIdx.x >> 5;
    #pragma unroll
    for (int r = 0; r < 4; r++)
        t[ty + r * 8][tx] = W[(size_t)(k0 + ty + r * 8) * Nd + n0 + tx];
    __syncthreads();
    #pragma unroll
    for (int r = 0; r < 4; r++) {
        float v = t[tx][ty + r * 8];
        __nv_bfloat16 h = __float2bfloat16_rn(v);
        __nv_bfloat16 l = __float2bfloat16_rn(v - __bfloat162float(h));
        size_t o = (size_t)(n0 + ty + r * 8) * Kd + k0 + tx;
        Th[o] = h; Tl[o] = l;
    }
}

// ===========================================================================
// mma.sync split-bf16 GEMM: C[M,N] fp32 = A[M,K] @ Bsrc^T  (Bsrc is [N,K])
// C = Ah*Bh + Ah*Bl + Al*Bh, fp32 accumulate in registers.
// 128x128 CTA tile, BK=64, 2-stage cp.async double buffer, 256 threads,
// 8 warps each 64(m) x 32(n).
// ===========================================================================
#define TK 64
#define TILE_BYTES (128 * 128)          // 128 rows x 128B (64 bf16)
#define STAGE_BYTES (4 * TILE_BYTES)    // Ah, Al, Bh, Bl
#define GEMM_SMEM (2 * STAGE_BYTES)     // 128 KB

__global__ __launch_bounds__(256, 1) void gemm_mma_kernel(
    const __nv_bfloat16* __restrict__ Ah, const __nv_bfloat16* __restrict__ Al,
    const __nv_bfloat16* __restrict__ Bh, const __nv_bfloat16* __restrict__ Bl,
    float* __restrict__ C, int M, int N, int K)
{
    extern __shared__ char smc[];
    const uint32_t sbase = smem_u32(smc);
    const int tid = threadIdx.x;
    const int wid = tid >> 5, lane = tid & 31;
    const int wm = wid & 1, wn = wid >> 1;      // warp grid 2 x 4
    const int m0 = blockIdx.y * 128;
    const int n0 = blockIdx.x * 128;

    const int nch = K / TK;

    // ---- async chunk loader: Ah, Al, Bh, Bl tiles into stage s ----
    auto load_chunk = [&](int kc, int s) {
        const uint32_t base = sbase + (uint32_t)s * STAGE_BYTES;
        const __nv_bfloat16* srcs[4] = {Ah, Al, Bh, Bl};
        const int row0s[4] = {m0, m0, n0, n0};
        #pragma unroll
        for (int t = 0; t < 4; t++) {
            const __nv_bfloat16* src = srcs[t] + (size_t)kc * TK;
            const int row0 = row0s[t];
            const uint32_t dst = base + (uint32_t)t * TILE_BYTES;
            #pragma unroll
            for (int g4 = 0; g4 < 4; g4++) {
                int g = tid + g4 * 256;         // 1024 x 16B granules
                int r = g >> 3, c = g & 7;
                const __nv_bfloat16* gp = src + (size_t)(row0 + r) * K + c * 8;
                uint32_t off = swz((uint32_t)((r << 7) + (c << 4)));
                CP_ASYNC16(dst + off, gp);
            }
        }
    };

    float acc[4][4][4];
    #pragma unroll
    for (int mi = 0; mi < 4; mi++)
        #pragma unroll
        for (int ni = 0; ni < 4; ni++)
            #pragma unroll
            for (int r = 0; r < 4; r++) acc[mi][ni][r] = 0.f;

    // per-thread ldmatrix row components (same formula for A and B x4 loads)
    const uint32_t lrow = (uint32_t)(lane & 15);
    const uint32_t lcol = (uint32_t)((lane >> 4) << 4);   // 0 or 16 bytes

    load_chunk(0, 0);
    CP_COMMIT();

    for (int i = 0; i < nch; i++) {
        if (i + 1 < nch) {
            load_chunk(i + 1, (i + 1) & 1);
            CP_COMMIT();
            CP_WAIT(1);
        } else {
            CP_WAIT(0);
        }
        __syncthreads();

        const uint32_t st = sbase + (uint32_t)(i & 1) * STAGE_BYTES;
        const uint32_t tAh = st;
        const uint32_t tAl = st + TILE_BYTES;
        const uint32_t tBh = st + 2 * TILE_BYTES;
        const uint32_t tBl = st + 3 * TILE_BYTES;

        #pragma unroll
        for (int ks = 0; ks < 4; ks++) {
            const uint32_t kb = (uint32_t)(ks << 5) + lcol;   // bytes within row
            uint32_t fAh[4][4], fAl[4][4], fBh[2][4], fBl[2][4];
            #pragma unroll
            for (int mi = 0; mi < 4; mi++) {
                uint32_t ro = ((uint32_t)(wm * 64 + mi * 16) + lrow) << 7;
                uint32_t ad = swz(ro + kb);
                LDSM_X4(fAh[mi][0], fAh[mi][1], fAh[mi][2], fAh[mi][3], tAh + ad);
                LDSM_X4(fAl[mi][0], fAl[mi][1], fAl[mi][2], fAl[mi][3], tAl + ad);
            }
            #pragma unroll
            for (int j = 0; j < 2; j++) {
                uint32_t ro = ((uint32_t)(wn * 32 + j * 16) + lrow) << 7;
                uint32_t ad = swz(ro + kb);
                LDSM_X4(fBh[j][0], fBh[j][1], fBh[j][2], fBh[j][3], tBh + ad);
                LDSM_X4(fBl[j][0], fBl[j][1], fBl[j][2], fBl[j][3], tBl + ad);
            }
            #pragma unroll
            for (int mi = 0; mi < 4; mi++) {
                #pragma unroll
                for (int ni = 0; ni < 4; ni++) {
                    const int j = ni >> 1, p = ni & 1;
                    MMA_BF16(acc[mi][ni], fAh[mi], fBh[j][p], fBh[j][2 + p]);
                    MMA_BF16(acc[mi][ni], fAh[mi], fBl[j][p], fBl[j][2 + p]);
                    MMA_BF16(acc[mi][ni], fAl[mi], fBh[j][p], fBh[j][2 + p]);
                }
            }
        }
        __syncthreads();
    }

    // epilogue
    float* Cw = C + (size_t)(m0 + wm * 64) * N + n0 + wn * 32;
    const int rq = lane >> 2, cq = (lane & 3) << 1;
    #pragma unroll
    for (int mi = 0; mi < 4; mi++) {
        #pragma unroll
        for (int ni = 0; ni < 4; ni++) {
            float2 v0 = make_float2(acc[mi][ni][0], acc[mi][ni][1]);
            float2 v1 = make_float2(acc[mi][ni][2], acc[mi][ni][3]);
            *(float2*)(Cw + (size_t)(mi * 16 + rq) * N + ni * 8 + cq)     = v0;
            *(float2*)(Cw + (size_t)(mi * 16 + rq + 8) * N + ni * 8 + cq) = v1;
        }
    }
}

// ===========================================================================
// RoPE: in-place on Q [tok, 32, 128] and K [tok, 8, 128]
// ===========================================================================
__global__ __launch_bounds__(256) void rope_kernel(
    float* __restrict__ Q, float* __restrict__ K,
    const int* __restrict__ pos32)
{
    const int token = blockIdx.x;
    const int pidx = g_pos_is64 ? (token << 1) : token;
    const float p = (float)pos32[pidx];
    const int tid = threadIdx.x;

    float* Qb = Q + (size_t)token * (NH * HD);
    for (int idx = tid; idx < NH * 64; idx += 256) {
        int h = idx >> 6, i = idx & 63;
        float inv = powf(10000.0f, -(float)(2 * i) * (1.0f / 128.0f));
        float sv, cv;
        sincosf(p * inv, &sv, &cv);
        float x1 = Qb[h * HD + i];
        float x2 = Qb[h * HD + i + 64];
        Qb[h * HD + i]      = x1 * cv - x2 * sv;
        Qb[h * HD + i + 64] = x2 * cv + x1 * sv;
    }

    float* Kb = K + (size_t)token * (NKV * HD);
    for (int idx = tid; idx < NKV * 64; idx += 256) {
        int h = idx >> 6, i = idx & 63;
        float inv = powf(10000.0f, -(float)(2 * i) * (1.0f / 128.0f));
        float sv, cv;
        sincosf(p * inv, &sv, &cv);
        float x1 = Kb[h * HD + i];
        float x2 = Kb[h * HD + i + 64];
        Kb[h * HD + i]      = x1 * cv - x2 * sv;
        Kb[h * HD + i + 64] = x2 * cv + x1 * sv;
    }
}

// ===========================================================================
// Flash attention (non-causal), fp32 SIMT (unchanged, known correct)
// ===========================================================================
#define QS 132
#define PS 68
#define ATT_SMEM_FLOATS (64 * QS * 2 + 64 * PS + 192)
#define ATT_SMEM_BYTES (ATT_SMEM_FLOATS * 4)

__global__ __launch_bounds__(256) void attn_kernel(
    const float* __restrict__ Q, const float* __restrict__ K,
    const float* __restrict__ V, float* __restrict__ O)
{
    extern __shared__ float smf[];
    float* Qs  = smf;
    float* KVs = Qs + 64 * QS;
    float* Ps  = KVs + 64 * QS;
    float* m_s  = Ps + 64 * PS;
    float* l_s  = m_s + 64;
    float* sc_s = l_s + 64;

    const int qt = blockIdx.x;
    const int h  = blockIdx.y;
    const int b  = blockIdx.z;
    const int kvh = h >> 2;

    const int tid = threadIdx.x;
    const int tq = tid >> 4;
    const int tx = tid & 15;
    const int w = tid >> 5, lane = tid & 31;

    const float scale = 0.08838834764831845f;

    const float* Qg = Q + (((size_t)b * S_ + (size_t)qt * 64) * NH + h) * HD;
    for (int i = tid; i < 64 * 32; i += 256) {
        int r = i >> 5, c4 = (i & 31) << 2;
        *(float4*)(Qs + r * QS + c4) =
            *(const float4*)(Qg + (size_t)r * (NH * HD) + c4);
    }
    if (tid < 64) { m_s[tid] = -INFINITY; l_s[tid] = 0.f; }

    float o_acc[4][8];
    #pragma unroll
    for (int i = 0; i < 4; i++)
        #pragma unroll
        for (int j = 0; j < 8; j++) o_acc[i][j] = 0.f;

    const float* Kg = K + ((size_t)b * S_ * NKV + kvh) * HD;
    const float* Vg = V + ((size_t)b * S_ * NKV + kvh) * HD;
    const size_t kvstride = (size_t)NKV * HD;

    for (int kt = 0; kt < S_ / 64; kt++) {
        __syncthreads();
        for (int i = tid; i < 64 * 32; i += 256) {
            int r = i >> 5, c4 = (i & 31) << 2;
            *(float4*)(KVs + r * QS + c4) =
                *(const float4*)(Kg + (size_t)(kt * 64 + r) * kvstride + c4);
        }
        __syncthreads();

        float s_acc[4][4];
        #pragma unroll
        for (int i = 0; i < 4; i++)
            #pragma unroll
            for (int j = 0; j < 4; j++) s_acc[i][j] = 0.f;

        for (int d = 0; d < HD; d += 4) {
            float4 qa[4], kb[4];
            #pragma unroll
            for (int i = 0; i < 4; i++)
                qa[i] = *(const float4*)(&Qs[(tq * 4 + i) * QS + d]);
            #pragma unroll
            for (int j = 0; j < 4; j++)
                kb[j] = *(const float4*)(&KVs[(tx + 16 * j) * QS + d]);
            #pragma unroll
            for (int i = 0; i < 4; i++)
                #pragma unroll
                for (int j = 0; j < 4; j++) {
                    s_acc[i][j] = fmaf(qa[i].x, kb[j].x, s_acc[i][j]);
                    s_acc[i][j] = fmaf(qa[i].y, kb[j].y, s_acc[i][j]);
                    s_acc[i][j] = fmaf(qa[i].z, kb[j].z, s_acc[i][j]);
                    s_acc[i][j] = fmaf(qa[i].w, kb[j].w, s_acc[i][j]);
                }
        }
        #pragma unroll
        for (int i = 0; i < 4; i++)
            #pragma unroll
            for (int j = 0; j < 4; j++)
                Ps[(tq * 4 + i) * PS + tx + 16 * j] = s_acc[i][j] * scale;
        __syncthreads();

        for (int rr = 0; rr < 8; rr++) {
            int r = w * 8 + rr;
            float v0 = Ps[r * PS + lane];
            float v1 = Ps[r * PS + lane + 32];
            float mx = fmaxf(v0, v1);
            #pragma unroll
            for (int off = 16; off > 0; off >>= 1)
                mx = fmaxf(mx, __shfl_xor_sync(0xffffffffu, mx, off));
            float m_old = m_s[r];
            float m_new = fmaxf(m_old, mx);
            float p0 = __expf(v0 - m_new);
            float p1 = __expf(v1 - m_new);
            Ps[r * PS + lane]      = p0;
            Ps[r * PS + lane + 32] = p1;
            float sm2 = p0 + p1;
            #pragma unroll
            for (int off = 16; off > 0; off >>= 1)
                sm2 += __shfl_xor_sync(0xffffffffu, sm2, off);
            if (lane == 0) {
                float scf = __expf(m_old - m_new);
                sc_s[r] = scf;
                l_s[r] = l_s[r] * scf + sm2;
                m_s[r] = m_new;
            }
        }
        __syncthreads();

        float rs[4];
        #pragma unroll
        for (int i = 0; i < 4; i++) rs[i] = sc_s[tq * 4 + i];
        #pragma unroll
        for (int i = 0; i < 4; i++)
            #pragma unroll
            for (int j = 0; j < 8; j++) o_acc[i][j] *= rs[i];

        for (int i = tid; i < 64 * 32; i += 256) {
            int r = i >> 5, c4 = (i & 31) << 2;
            *(float4*)(KVs + r * QS + c4) =
                *(const float4*)(Vg + (size_t)(kt * 64 + r) * kvstride + c4);
        }
        __syncthreads();

        for (int k = 0; k < 64; k += 4) {
            float4 pa[4];
            #pragma unroll
            for (int i = 0; i < 4; i++)
                pa[i] = *(const float4*)(&Ps[(tq * 4 + i) * PS + k]);
            #pragma unroll
            for (int kk = 0; kk < 4; kk++) {
                float pv[8];
                #pragma unroll
                for (int j = 0; j < 8; j++)
                    pv[j] = KVs[(k + kk) * QS + tx + 16 * j];
                float pav[4] = {
                    kk == 0 ? pa[0].x : kk == 1 ? pa[0].y : kk == 2 ? pa[0].z : pa[0].w,
                    kk == 0 ? pa[1].x : kk == 1 ? pa[1].y : kk == 2 ? pa[1].z : pa[1].w,
                    kk == 0 ? pa[2].x : kk == 1 ? pa[2].y : kk == 2 ? pa[2].z : pa[2].w,
                    kk == 0 ? pa[3].x : kk == 1 ? pa[3].y : kk == 2 ? pa[3].z : pa[3].w
                };
                #pragma unroll
                for (int i = 0; i < 4; i++)
                    #pragma unroll
                    for (int j = 0; j < 8; j++)
                        o_acc[i][j] = fmaf(pav[i], pv[j], o_acc[i][j]);
            }
        }
    }
    __syncthreads();

    float* Og = O + (((size_t)b * S_ + (size_t)qt * 64) * NH + h) * HD;
    #pragma unroll
    for (int i = 0; i < 4; i++) {
        float inv_l = 1.0f / l_s[tq * 4 + i];
        #pragma unroll
        for (int j = 0; j < 8; j++)
            Og[(size_t)(tq * 4 + i) * (NH * HD) + tx + 16 * j] =
                o_acc[i][j] * inv_l;
    }
}

// ===========================================================================
// Launch
// ===========================================================================
extern "C" void kernel_launch(void* const* d_in, const int* in_sizes, int n_in,
                              void* d_out, int out_size)
{
    const float* X     = (const float*)d_in[0];
    const int*   pos32 = (const int*)d_in[1];
    const float* Wq = (const float*)d_in[2];
    const float* Wk = (const float*)d_in[3];
    const float* Wv = (const float*)d_in[4];
    const float* Wo = (const float*)d_in[5];
    float* out = (float*)d_out;

    float *Qp, *Kp, *Vp, *Ap;
    cudaGetSymbolAddress((void**)&Qp, g_Q);
    cudaGetSymbolAddress((void**)&Kp, g_K);
    cudaGetSymbolAddress((void**)&Vp, g_V);
    cudaGetSymbolAddress((void**)&Ap, g_A);
    __nv_bfloat16 *Xh, *Xl, *Ahp, *Alp;
    __nv_bfloat16 *Wqh, *Wql, *Wkh, *Wkl, *Wvh, *Wvl, *Woh, *Wol;
    cudaGetSymbolAddress((void**)&Xh, g_Xh);   cudaGetSymbolAddress((void**)&Xl, g_Xl);
    cudaGetSymbolAddress((void**)&Ahp, g_Ah);  cudaGetSymbolAddress((void**)&Alp, g_Al);
    cudaGetSymbolAddress((void**)&Wqh, g_Wqh); cudaGetSymbolAddress((void**)&Wql, g_Wql);
    cudaGetSymbolAddress((void**)&Wkh, g_Wkh); cudaGetSymbolAddress((void**)&Wkl, g_Wkl);
    cudaGetSymbolAddress((void**)&Wvh, g_Wvh); cudaGetSymbolAddress((void**)&Wvl, g_Wvl);
    cudaGetSymbolAddress((void**)&Woh, g_Woh); cudaGetSymbolAddress((void**)&Wol, g_Wol);

    cudaFuncSetAttribute(attn_kernel,
                         cudaFuncAttributeMaxDynamicSharedMemorySize, ATT_SMEM_BYTES);
    cudaFuncSetAttribute(gemm_mma_kernel,
                         cudaFuncAttributeMaxDynamicSharedMemorySize, GEMM_SMEM);

    detect_pos_kernel<<<1, 1>>>(pos32);

    // split X; transpose+split weights
    const int nX4 = TOKENS * HID / 4;
    split_kernel<<<(nX4 + 255) / 256, 256>>>(X, Xh, Xl, nX4);
    transpose_split_kernel<<<dim3(HID / 32, HID / 32), 256>>>(Wq, Wqh, Wql, HID, HID);
    transpose_split_kernel<<<dim3(KVDIM / 32, HID / 32), 256>>>(Wk, Wkh, Wkl, HID, KVDIM);
    transpose_split_kernel<<<dim3(KVDIM / 32, HID / 32), 256>>>(Wv, Wvh, Wvl, HID, KVDIM);
    transpose_split_kernel<<<dim3(HID / 32, HID / 32), 256>>>(Wo, Woh, Wol, HID, HID);

    // projections (mma.sync)
    gemm_mma_kernel<<<dim3(HID / 128, TOKENS / 128), 256, GEMM_SMEM>>>(
        Xh, Xl, Wqh, Wql, Qp, TOKENS, HID, HID);
    gemm_mma_kernel<<<dim3(KVDIM / 128, TOKENS / 128), 256, GEMM_SMEM>>>(
        Xh, Xl, Wkh, Wkl, Kp, TOKENS, KVDIM, HID);
    gemm_mma_kernel<<<dim3(KVDIM / 128, TOKENS / 128), 256, GEMM_SMEM>>>(
        Xh, Xl, Wvh, Wvl, Vp, TOKENS, KVDIM, HID);

    rope_kernel<<<TOKENS, 256>>>(Qp, Kp, pos32);
    attn_kernel<<<dim3(S_ / 64, NH, B_), 256, ATT_SMEM_BYTES>>>(Qp, Kp, Vp, Ap);

    // O projection (mma.sync)
    split_kernel<<<(nX4 + 255) / 256, 256>>>(Ap, Ahp, Alp, nX4);
    gemm_mma_kernel<<<dim3(HID / 128, TOKENS / 128), 256, GEMM_SMEM>>>(
        Ahp, Alp, Woh, Wol, out, TOKENS, HID, HID);
}

// round 5
// speedup vs baseline: 2.6225x; 1.4110x over previous
#include <cuda_runtime.h>
#include <cuda_bf16.h>
#include <math.h>
#include <stdint.h>

// ---------------------------------------------------------------------------
// GroupedQueryAttention, GB300 (harness PTX target compute_103: no tcgen05).
// Round 5: GEMMs (proven mma.sync split-bf16) + attention ALSO on mma.sync:
//   S = QhKh + QhKl + QlKh (fp32 acc), SIMT softmax -> split-bf16 P in smem,
//   O += PhVh + PhVl + PlVh with V pre-transposed (Vt[d][s]).
// ---------------------------------------------------------------------------

#define B_ 2
#define S_ 2048
#define HID 4096
#define NH 32
#define NKV 8
#define HD 128
#define TOKENS (B_ * S_)
#define KVDIM (NKV * HD)   // 1024

typedef __nv_bfloat16 bf16;

// fp32 activation scratch
__device__ float g_Q[TOKENS * NH * HD];
__device__ float g_K[TOKENS * NKV * HD];
__device__ float g_V[TOKENS * NKV * HD];
__device__ float g_A[TOKENS * NH * HD];
__device__ int   g_pos_is64;

// bf16 split scratch (GEMM inputs)
__device__ bf16 g_Xh[TOKENS * HID];
__device__ bf16 g_Xl[TOKENS * HID];
__device__ bf16 g_Ah[TOKENS * HID];
__device__ bf16 g_Al[TOKENS * HID];
__device__ bf16 g_Wqh[HID * HID];
__device__ bf16 g_Wql[HID * HID];
__device__ bf16 g_Wkh[KVDIM * HID];
__device__ bf16 g_Wkl[KVDIM * HID];
__device__ bf16 g_Wvh[KVDIM * HID];
__device__ bf16 g_Wvl[KVDIM * HID];
__device__ bf16 g_Woh[HID * HID];
__device__ bf16 g_Wol[HID * HID];

// bf16 split scratch (attention operands)
__device__ bf16 g_Qbh[TOKENS * NH * HD];   // rope'd Q hi
__device__ bf16 g_Qbl[TOKENS * NH * HD];   // rope'd Q lo
__device__ bf16 g_Kbh[TOKENS * NKV * HD];  // rope'd K hi
__device__ bf16 g_Kbl[TOKENS * NKV * HD];  // rope'd K lo
__device__ bf16 g_Vth[B_ * NKV * HD * S_]; // V transposed [b][kvh][d][s] hi
__device__ bf16 g_Vtl[B_ * NKV * HD * S_]; // lo

// ===========================================================================
// Helpers
// ===========================================================================
__device__ __forceinline__ uint32_t smem_u32(const void* p) {
    uint32_t a;
    asm("{ .reg .u64 t; cvta.to.shared.u64 t, %1; cvt.u32.u64 %0, t; }"
        : "=r"(a) : "l"(p));
    return a;
}
__device__ __forceinline__ uint32_t swz(uint32_t off) {
    return off ^ ((off >> 3) & 0x70);
}

#define CP_ASYNC16(dst, src) \
    asm volatile("cp.async.cg.shared.global [%0], [%1], 16;" \
        :: "r"(dst), "l"(src) : "memory")
#define CP_COMMIT() asm volatile("cp.async.commit_group;" ::: "memory")
#define CP_WAIT(n)  asm volatile("cp.async.wait_group %0;" :: "n"(n) : "memory")

#define LDSM_X4(r0, r1, r2, r3, addr) \
    asm volatile("ldmatrix.sync.aligned.m8n8.x4.shared.b16 {%0,%1,%2,%3}, [%4];" \
        : "=r"(r0), "=r"(r1), "=r"(r2), "=r"(r3) : "r"(addr))

#define MMA_BF16(d, a, b0v, b1v) \
    asm volatile("mma.sync.aligned.m16n8k16.row.col.f32.bf16.bf16.f32 " \
        "{%0,%1,%2,%3}, {%4,%5,%6,%7}, {%8,%9}, {%0,%1,%2,%3};" \
        : "+f"((d)[0]), "+f"((d)[1]), "+f"((d)[2]), "+f"((d)[3]) \
        : "r"((a)[0]), "r"((a)[1]), "r"((a)[2]), "r"((a)[3]), \
          "r"(b0v), "r"(b1v))

// ===========================================================================
// position_ids dtype probe
// ===========================================================================
__global__ void detect_pos_kernel(const int* __restrict__ p)
{
    if (threadIdx.x == 0 && blockIdx.x == 0)
        g_pos_is64 = (p[1] == 0 && p[3] == 0 && p[5] == 0 && p[7] == 0) ? 1 : 0;
}

// ===========================================================================
// Split fp32 -> (bf16 hi, bf16 lo)
// ===========================================================================
__global__ __launch_bounds__(256) void split_kernel(
    const float* __restrict__ x, bf16* __restrict__ h,
    bf16* __restrict__ l, int n4)
{
    int i = blockIdx.x * 256 + threadIdx.x;
    if (i >= n4) return;
    float4 v = *(const float4*)(x + (size_t)i * 4);
    bf16 h0 = __float2bfloat16_rn(v.x);
    bf16 h1 = __float2bfloat16_rn(v.y);
    bf16 h2 = __float2bfloat16_rn(v.z);
    bf16 h3 = __float2bfloat16_rn(v.w);
    bf16 l0 = __float2bfloat16_rn(v.x - __bfloat162float(h0));
    bf16 l1 = __float2bfloat16_rn(v.y - __bfloat162float(h1));
    bf16 l2 = __float2bfloat16_rn(v.z - __bfloat162float(h2));
    bf16 l3 = __float2bfloat16_rn(v.w - __bfloat162float(h3));
    __nv_bfloat162* H = (__nv_bfloat162*)(h + (size_t)i * 4);
    __nv_bfloat162* L = (__nv_bfloat162*)(l + (size_t)i * 4);
    H[0] = __nv_bfloat162(h0, h1); H[1] = __nv_bfloat162(h2, h3);
    L[0] = __nv_bfloat162(l0, l1); L[1] = __nv_bfloat162(l2, l3);
}

// ===========================================================================
// Transpose + split: W [Kd, Nd] fp32 -> Th/Tl [Nd, Kd] bf16
// ===========================================================================
__global__ __launch_bounds__(256) void transpose_split_kernel(
    const float* __restrict__ W, bf16* __restrict__ Th,
    bf16* __restrict__ Tl, int Kd, int Nd)
{
    __shared__ float t[32][33];
    const int n0 = blockIdx.x * 32, k0 = blockIdx.y * 32;
    const int tx = threadIdx.x & 31, ty = threadIdx.x >> 5;
    #pragma unroll
    for (int r = 0; r < 4; r++)
        t[ty + r * 8][tx] = W[(size_t)(k0 + ty + r * 8) * Nd + n0 + tx];
    __syncthreads();
    #pragma unroll
    for (int r = 0; r < 4; r++) {
        float v = t[tx][ty + r * 8];
        bf16 h = __float2bfloat16_rn(v);
        bf16 l = __float2bfloat16_rn(v - __bfloat162float(h));
        size_t o = (size_t)(n0 + ty + r * 8) * Kd + k0 + tx;
        Th[o] = h; Tl[o] = l;
    }
}

// ===========================================================================
// V transpose + split: V fp32 [b][s][kvh][d] -> Vt bf16 [b][kvh][d][s] hi/lo
// grid: (S_/32, HD/32, B_*NKV)
// ===========================================================================
__global__ __launch_bounds__(256) void transpose_split_v_kernel(
    const float* __restrict__ V, bf16* __restrict__ Vth, bf16* __restrict__ Vtl)
{
    __shared__ float t[32][33];
    const int s0 = blockIdx.x * 32, d0 = blockIdx.y * 32;
    const int bk = blockIdx.z;                 // b*NKV + kvh
    const int b = bk / NKV, kvh = bk % NKV;
    const int tx = threadIdx.x & 31, ty = threadIdx.x >> 5;
    #pragma unroll
    for (int r = 0; r < 4; r++) {
        int s = s0 + ty + r * 8;
        t[ty + r * 8][tx] = V[((size_t)(b * S_ + s) * NKV + kvh) * HD + d0 + tx];
    }
    __syncthreads();
    #pragma unroll
    for (int r = 0; r < 4; r++) {
        int d = d0 + ty + r * 8;
        float v = t[tx][ty + r * 8];           // = V[s0+tx][d]
        bf16 h = __float2bfloat16_rn(v);
        bf16 l = __float2bfloat16_rn(v - __bfloat162float(h));
        size_t o = ((size_t)bk * HD + d) * S_ + s0 + tx;
        Vth[o] = h; Vtl[o] = l;
    }
}

// ===========================================================================
// mma.sync split-bf16 GEMM (unchanged, proven): C = A @ Bsrc^T
// ===========================================================================
#define TK 64
#define TILE_BYTES (128 * 128)
#define STAGE_BYTES (4 * TILE_BYTES)
#define GEMM_SMEM (2 * STAGE_BYTES)

__global__ __launch_bounds__(256, 1) void gemm_mma_kernel(
    const bf16* __restrict__ Ah, const bf16* __restrict__ Al,
    const bf16* __restrict__ Bh, const bf16* __restrict__ Bl,
    float* __restrict__ C, int M, int N, int K)
{
    extern __shared__ char smc[];
    const uint32_t sbase = smem_u32(smc);
    const int tid = threadIdx.x;
    const int wid = tid >> 5, lane = tid & 31;
    const int wm = wid & 1, wn = wid >> 1;
    const int m0 = blockIdx.y * 128;
    const int n0 = blockIdx.x * 128;

    const int nch = K / TK;

    auto load_chunk = [&](int kc, int s) {
        const uint32_t base = sbase + (uint32_t)s * STAGE_BYTES;
        const bf16* srcs[4] = {Ah, Al, Bh, Bl};
        const int row0s[4] = {m0, m0, n0, n0};
        #pragma unroll
        for (int t = 0; t < 4; t++) {
            const bf16* src = srcs[t] + (size_t)kc * TK;
            const int row0 = row0s[t];
            const uint32_t dst = base + (uint32_t)t * TILE_BYTES;
            #pragma unroll
            for (int g4 = 0; g4 < 4; g4++) {
                int g = tid + g4 * 256;
                int r = g >> 3, c = g & 7;
                const bf16* gp = src + (size_t)(row0 + r) * K + c * 8;
                uint32_t off = swz((uint32_t)((r << 7) + (c << 4)));
                CP_ASYNC16(dst + off, gp);
            }
        }
    };

    float acc[4][4][4];
    #pragma unroll
    for (int mi = 0; mi < 4; mi++)
        #pragma unroll
        for (int ni = 0; ni < 4; ni++)
            #pragma unroll
            for (int r = 0; r < 4; r++) acc[mi][ni][r] = 0.f;

    const uint32_t lrow = (uint32_t)(lane & 15);
    const uint32_t lcol = (uint32_t)((lane >> 4) << 4);

    load_chunk(0, 0);
    CP_COMMIT();

    for (int i = 0; i < nch; i++) {
        if (i + 1 < nch) {
            load_chunk(i + 1, (i + 1) & 1);
            CP_COMMIT();
            CP_WAIT(1);
        } else {
            CP_WAIT(0);
        }
        __syncthreads();

        const uint32_t st = sbase + (uint32_t)(i & 1) * STAGE_BYTES;
        const uint32_t tAh = st;
        const uint32_t tAl = st + TILE_BYTES;
        const uint32_t tBh = st + 2 * TILE_BYTES;
        const uint32_t tBl = st + 3 * TILE_BYTES;

        #pragma unroll
        for (int ks = 0; ks < 4; ks++) {
            const uint32_t kb = (uint32_t)(ks << 5) + lcol;
            uint32_t fAh[4][4], fAl[4][4], fBh[2][4], fBl[2][4];
            #pragma unroll
            for (int mi = 0; mi < 4; mi++) {
                uint32_t ro = ((uint32_t)(wm * 64 + mi * 16) + lrow) << 7;
                uint32_t ad = swz(ro + kb);
                LDSM_X4(fAh[mi][0], fAh[mi][1], fAh[mi][2], fAh[mi][3], tAh + ad);
                LDSM_X4(fAl[mi][0], fAl[mi][1], fAl[mi][2], fAl[mi][3], tAl + ad);
            }
            #pragma unroll
            for (int j = 0; j < 2; j++) {
                uint32_t ro = ((uint32_t)(wn * 32 + j * 16) + lrow) << 7;
                uint32_t ad = swz(ro + kb);
                LDSM_X4(fBh[j][0], fBh[j][1], fBh[j][2], fBh[j][3], tBh + ad);
                LDSM_X4(fBl[j][0], fBl[j][1], fBl[j][2], fBl[j][3], tBl + ad);
            }
            #pragma unroll
            for (int mi = 0; mi < 4; mi++) {
                #pragma unroll
                for (int ni = 0; ni < 4; ni++) {
                    const int j = ni >> 1, p = ni & 1;
                    MMA_BF16(acc[mi][ni], fAh[mi], fBh[j][p], fBh[j][2 + p]);
                    MMA_BF16(acc[mi][ni], fAh[mi], fBl[j][p], fBl[j][2 + p]);
                    MMA_BF16(acc[mi][ni], fAl[mi], fBh[j][p], fBh[j][2 + p]);
                }
            }
        }
        __syncthreads();
    }

    float* Cw = C + (size_t)(m0 + wm * 64) * N + n0 + wn * 32;
    const int rq = lane >> 2, cq = (lane & 3) << 1;
    #pragma unroll
    for (int mi = 0; mi < 4; mi++) {
        #pragma unroll
        for (int ni = 0; ni < 4; ni++) {
            float2 v0 = make_float2(acc[mi][ni][0], acc[mi][ni][1]);
            float2 v1 = make_float2(acc[mi][ni][2], acc[mi][ni][3]);
            *(float2*)(Cw + (size_t)(mi * 16 + rq) * N + ni * 8 + cq)     = v0;
            *(float2*)(Cw + (size_t)(mi * 16 + rq + 8) * N + ni * 8 + cq) = v1;
        }
    }
}

// ===========================================================================
// RoPE + split: read fp32 Q/K, rotate, write split bf16 Q/K
// ===========================================================================
__global__ __launch_bounds__(256) void rope_split_kernel(
    const float* __restrict__ Q, const float* __restrict__ K,
    const int* __restrict__ pos32,
    bf16* __restrict__ Qbh, bf16* __restrict__ Qbl,
    bf16* __restrict__ Kbh, bf16* __restrict__ Kbl)
{
    const int token = blockIdx.x;
    const int pidx = g_pos_is64 ? (token << 1) : token;
    const float p = (float)pos32[pidx];
    const int tid = threadIdx.x;

    const float* Qb = Q + (size_t)token * (NH * HD);
    bf16* Qh = Qbh + (size_t)token * (NH * HD);
    bf16* Ql = Qbl + (size_t)token * (NH * HD);
    for (int idx = tid; idx < NH * 64; idx += 256) {
        int h = idx >> 6, i = idx & 63;
        float inv = powf(10000.0f, -(float)(2 * i) * (1.0f / 128.0f));
        float sv, cv;
        sincosf(p * inv, &sv, &cv);
        float x1 = Qb[h * HD + i];
        float x2 = Qb[h * HD + i + 64];
        float y1 = x1 * cv - x2 * sv;
        float y2 = x2 * cv + x1 * sv;
        bf16 h1 = __float2bfloat16_rn(y1);
        bf16 h2 = __float2bfloat16_rn(y2);
        Qh[h * HD + i]      = h1;
        Qh[h * HD + i + 64] = h2;
        Ql[h * HD + i]      = __float2bfloat16_rn(y1 - __bfloat162float(h1));
        Ql[h * HD + i + 64] = __float2bfloat16_rn(y2 - __bfloat162float(h2));
    }

    const float* Kb = K + (size_t)token * (NKV * HD);
    bf16* Kh = Kbh + (size_t)token * (NKV * HD);
    bf16* Kl = Kbl + (size_t)token * (NKV * HD);
    for (int idx = tid; idx < NKV * 64; idx += 256) {
        int h = idx >> 6, i = idx & 63;
        float inv = powf(10000.0f, -(float)(2 * i) * (1.0f / 128.0f));
        float sv, cv;
        sincosf(p * inv, &sv, &cv);
        float x1 = Kb[h * HD + i];
        float x2 = Kb[h * HD + i + 64];
        float y1 = x1 * cv - x2 * sv;
        float y2 = x2 * cv + x1 * sv;
        bf16 h1 = __float2bfloat16_rn(y1);
        bf16 h2 = __float2bfloat16_rn(y2);
        Kh[h * HD + i]      = h1;
        Kh[h * HD + i + 64] = h2;
        Kl[h * HD + i]      = __float2bfloat16_rn(y1 - __bfloat162float(h1));
        Kl[h * HD + i + 64] = __float2bfloat16_rn(y2 - __bfloat162float(h2));
    }
}

// ===========================================================================
// mma.sync flash attention (non-causal)
// 64 q-rows/CTA, 64-key tiles, 8 warps (2m x 4n), double-buffered K/V.
// smem: Q 32K | K[2] 64K | V[2] 64K | P 16K | Ps 17K | stats
// ===========================================================================
#define ACH 8192                        // one 64-row x 128B chunk
#define AT_Q_OFF  0
#define AT_K_OFF  32768
#define AT_V_OFF  (32768 + 65536)       // 98304
#define AT_P_OFF  (98304 + 65536)       // 163840
#define AT_PS_OFF (163840 + 16384)      // 180224
#define AT_ST_OFF (180224 + 17408)      // 197632
#define AT_SMEM   (197632 + 768)

__global__ __launch_bounds__(256, 1) void attn_mma_kernel(
    const bf16* __restrict__ Qbh, const bf16* __restrict__ Qbl,
    const bf16* __restrict__ Kbh, const bf16* __restrict__ Kbl,
    const bf16* __restrict__ Vth, const bf16* __restrict__ Vtl,
    float* __restrict__ O)
{
    extern __shared__ char smc[];
    const uint32_t sb = smem_u32(smc);
    const int qt = blockIdx.x;          // 0..31
    const int h  = blockIdx.y;          // 0..31
    const int b  = blockIdx.z;
    const int kvh = h >> 2;
    const int bk = b * NKV + kvh;

    const int tid = threadIdx.x;
    const int wid = tid >> 5, lane = tid & 31;
    const int wm = wid & 1, wn = wid >> 1;
    const uint32_t lrow = (uint32_t)(lane & 15);
    const uint32_t lcol = (uint32_t)((lane >> 4) << 4);
    const int rq = lane >> 2, cq = (lane & 3) << 1;

    float* Ps  = (float*)(smc + AT_PS_OFF);   // [64][68]
    float* m_s  = (float*)(smc + AT_ST_OFF);
    float* l_s  = m_s + 64;
    float* sc_s = l_s + 64;

    const float scale = 0.08838834764831845f;  // 1/sqrt(128)

    // ---- Q load (once): 2048 granules, layout [hl][c][r][gr] ----
    {
        const bf16* Qsrc[2] = {Qbh, Qbl};
        #pragma unroll
        for (int g4 = 0; g4 < 8; g4++) {
            int g = tid + g4 * 256;
            int hl = g >> 10, rem = g & 1023;
            int c = rem >> 9, r = (rem >> 3) & 63, gr = rem & 7;
            const bf16* gp = Qsrc[hl] +
                ((size_t)((b * S_ + qt * 64 + r) * NH + h) * HD + c * 64 + gr * 8);
            uint32_t dst = sb + AT_Q_OFF + (uint32_t)(hl * 2 + c) * ACH +
                           swz((uint32_t)((r << 7) + (gr << 4)));
            CP_ASYNC16(dst, gp);
        }
    }

    // ---- K/V tile loader ----
    auto load_kv = [&](int kt, int s) {
        const bf16* Ks[2] = {Kbh, Kbl};
        #pragma unroll
        for (int g4 = 0; g4 < 8; g4++) {
            int g = tid + g4 * 256;
            int hl = g >> 10, rem = g & 1023;
            int c = rem >> 9, r = (rem >> 3) & 63, gr = rem & 7;
            const bf16* gp = Ks[hl] +
                ((size_t)((b * S_ + kt * 64 + r) * NKV + kvh) * HD + c * 64 + gr * 8);
            uint32_t dst = sb + AT_K_OFF + (uint32_t)s * 32768 +
                           (uint32_t)(hl * 2 + c) * ACH +
                           swz((uint32_t)((r << 7) + (gr << 4)));
            CP_ASYNC16(dst, gp);
        }
        const bf16* Vs[2] = {Vth, Vtl};
        #pragma unroll
        for (int g4 = 0; g4 < 8; g4++) {
            int g = tid + g4 * 256;
            int hl = g >> 10, rem = g & 1023;
            int d = rem >> 3, gr = rem & 7;
            const bf16* gp = Vs[hl] +
                ((size_t)bk * HD + d) * S_ + kt * 64 + gr * 8;
            uint32_t dst = sb + AT_V_OFF + (uint32_t)s * 32768 +
                           (uint32_t)hl * 16384 +
                           swz((uint32_t)((d << 7) + (gr << 4)));
            CP_ASYNC16(dst, gp);
        }
    };

    load_kv(0, 0);
    CP_COMMIT();
    if (tid < 64) { m_s[tid] = -INFINITY; l_s[tid] = 0.f; }

    float o_acc[2][4][4];
    #pragma unroll
    for (int mi = 0; mi < 2; mi++)
        #pragma unroll
        for (int ni = 0; ni < 4; ni++)
            #pragma unroll
            for (int r = 0; r < 4; r++) o_acc[mi][ni][r] = 0.f;

    for (int kt = 0; kt < S_ / 64; kt++) {
        const int st = kt & 1;
        if (kt + 1 < S_ / 64) {
            load_kv(kt + 1, st ^ 1);
            CP_COMMIT();
            CP_WAIT(1);
        } else {
            CP_WAIT(0);
        }
        __syncthreads();

        // ---- S = Q K^T (3 products) ----
        float s_acc[2][2][4];
        #pragma unroll
        for (int mi = 0; mi < 2; mi++)
            #pragma unroll
            for (int ni = 0; ni < 2; ni++)
                #pragma unroll
                for (int r = 0; r < 4; r++) s_acc[mi][ni][r] = 0.f;

        const uint32_t Kbase = sb + AT_K_OFF + (uint32_t)st * 32768;
        #pragma unroll
        for (int c = 0; c < 2; c++) {
            const uint32_t qch = sb + AT_Q_OFF + (uint32_t)c * ACH;
            const uint32_t qcl = qch + 2 * ACH;
            const uint32_t kch = Kbase + (uint32_t)c * ACH;
            const uint32_t kcl = kch + 2 * ACH;
            #pragma unroll
            for (int ks = 0; ks < 4; ks++) {
                const uint32_t kb = (uint32_t)(ks << 5) + lcol;
                uint32_t fQh[2][4], fQl[2][4], fKh[4], fKl[4];
                #pragma unroll
                for (int mi = 0; mi < 2; mi++) {
                    uint32_t ad = swz((((uint32_t)(wm * 32 + mi * 16) + lrow) << 7) + kb);
                    LDSM_X4(fQh[mi][0], fQh[mi][1], fQh[mi][2], fQh[mi][3], qch + ad);
                    LDSM_X4(fQl[mi][0], fQl[mi][1], fQl[mi][2], fQl[mi][3], qcl + ad);
                }
                {
                    uint32_t ad = swz((((uint32_t)(wn * 16) + lrow) << 7) + kb);
                    LDSM_X4(fKh[0], fKh[1], fKh[2], fKh[3], kch + ad);
                    LDSM_X4(fKl[0], fKl[1], fKl[2], fKl[3], kcl + ad);
                }
                #pragma unroll
                for (int mi = 0; mi < 2; mi++)
                    #pragma unroll
                    for (int ni = 0; ni < 2; ni++) {
                        MMA_BF16(s_acc[mi][ni], fQh[mi], fKh[ni], fKh[2 + ni]);
                        MMA_BF16(s_acc[mi][ni], fQh[mi], fKl[ni], fKl[2 + ni]);
                        MMA_BF16(s_acc[mi][ni], fQl[mi], fKh[ni], fKh[2 + ni]);
                    }
            }
        }

        // ---- store scaled S to Ps ----
        #pragma unroll
        for (int mi = 0; mi < 2; mi++) {
            const int row = wm * 32 + mi * 16 + rq;
            #pragma unroll
            for (int ni = 0; ni < 2; ni++) {
                const int col = wn * 16 + ni * 8 + cq;
                Ps[row * 68 + col]           = s_acc[mi][ni][0] * scale;
                Ps[row * 68 + col + 1]       = s_acc[mi][ni][1] * scale;
                Ps[(row + 8) * 68 + col]     = s_acc[mi][ni][2] * scale;
                Ps[(row + 8) * 68 + col + 1] = s_acc[mi][ni][3] * scale;
            }
        }
        __syncthreads();

        // ---- SIMT online softmax -> split bf16 P ----
        {
            const int r = wid * 8;   // rows wid*8 .. wid*8+7
            #pragma unroll
            for (int rr = 0; rr < 8; rr++) {
                const int row = r + rr;
                float v0 = Ps[row * 68 + lane];
                float v1 = Ps[row * 68 + lane + 32];
                float mx = fmaxf(v0, v1);
                #pragma unroll
                for (int off = 16; off > 0; off >>= 1)
                    mx = fmaxf(mx, __shfl_xor_sync(0xffffffffu, mx, off));
                float m_old = m_s[row];
                float m_new = fmaxf(m_old, mx);
                float p0 = __expf(v0 - m_new);
                float p1 = __expf(v1 - m_new);
                bf16 ph0 = __float2bfloat16_rn(p0);
                bf16 ph1 = __float2bfloat16_rn(p1);
                bf16 pl0 = __float2bfloat16_rn(p0 - __bfloat162float(ph0));
                bf16 pl1 = __float2bfloat16_rn(p1 - __bfloat162float(ph1));
                uint32_t o0 = swz((uint32_t)(row * 128 + lane * 2));
                uint32_t o1 = swz((uint32_t)(row * 128 + lane * 2 + 64));
                *(bf16*)(smc + AT_P_OFF + o0)        = ph0;
                *(bf16*)(smc + AT_P_OFF + o1)        = ph1;
                *(bf16*)(smc + AT_P_OFF + 8192 + o0) = pl0;
                *(bf16*)(smc + AT_P_OFF + 8192 + o1) = pl1;
                float sm2 = p0 + p1;
                #pragma unroll
                for (int off = 16; off > 0; off >>= 1)
                    sm2 += __shfl_xor_sync(0xffffffffu, sm2, off);
                if (lane == 0) {
                    float scf = __expf(m_old - m_new);
                    sc_s[row] = scf;
                    l_s[row] = l_s[row] * scf + sm2;
                    m_s[row] = m_new;
                }
            }
        }
        __syncthreads();

        // ---- rescale O ----
        #pragma unroll
        for (int mi = 0; mi < 2; mi++) {
            const int r0 = wm * 32 + mi * 16 + rq;
            const float f0 = sc_s[r0], f1 = sc_s[r0 + 8];
            #pragma unroll
            for (int ni = 0; ni < 4; ni++) {
                o_acc[mi][ni][0] *= f0; o_acc[mi][ni][1] *= f0;
                o_acc[mi][ni][2] *= f1; o_acc[mi][ni][3] *= f1;
            }
        }

        // ---- O += P V (3 products) ----
        const uint32_t Pbh = sb + AT_P_OFF, Pbl = Pbh + 8192;
        const uint32_t Vbh = sb + AT_V_OFF + (uint32_t)st * 32768;
        const uint32_t Vbl = Vbh + 16384;
        #pragma unroll
        for (int ks = 0; ks < 4; ks++) {
            const uint32_t kb = (uint32_t)(ks << 5) + lcol;
            uint32_t fPh[2][4], fPl[2][4], fVh[2][4], fVl[2][4];
            #pragma unroll
            for (int mi = 0; mi < 2; mi++) {
                uint32_t ad = swz((((uint32_t)(wm * 32 + mi * 16) + lrow) << 7) + kb);
                LDSM_X4(fPh[mi][0], fPh[mi][1], fPh[mi][2], fPh[mi][3], Pbh + ad);
                LDSM_X4(fPl[mi][0], fPl[mi][1], fPl[mi][2], fPl[mi][3], Pbl + ad);
            }
            #pragma unroll
            for (int j = 0; j < 2; j++) {
                uint32_t ad = swz((((uint32_t)(wn * 32 + j * 16) + lrow) << 7) + kb);
                LDSM_X4(fVh[j][0], fVh[j][1], fVh[j][2], fVh[j][3], Vbh + ad);
                LDSM_X4(fVl[j][0], fVl[j][1], fVl[j][2], fVl[j][3], Vbl + ad);
            }
            #pragma unroll
            for (int mi = 0; mi < 2; mi++)
                #pragma unroll
                for (int ni = 0; ni < 4; ni++) {
                    const int j = ni >> 1, p = ni & 1;
                    MMA_BF16(o_acc[mi][ni], fPh[mi], fVh[j][p], fVh[j][2 + p]);
                    MMA_BF16(o_acc[mi][ni], fPh[mi], fVl[j][p], fVl[j][2 + p]);
                    MMA_BF16(o_acc[mi][ni], fPl[mi], fVh[j][p], fVh[j][2 + p]);
                }
        }
        __syncthreads();   // protect stage/P/Ps reuse
    }

    // ---- epilogue: normalize, write O ----
    #pragma unroll
    for (int mi = 0; mi < 2; mi++) {
        const int r0 = wm * 32 + mi * 16 + rq;
        const float inv0 = 1.0f / l_s[r0];
        const float inv1 = 1.0f / l_s[r0 + 8];
        float* O0 = O + ((size_t)(b * S_ + qt * 64 + r0) * NH + h) * HD;
        float* O1 = O + ((size_t)(b * S_ + qt * 64 + r0 + 8) * NH + h) * HD;
        #pragma unroll
        for (int ni = 0; ni < 4; ni++) {
            const int col = wn * 32 + ni * 8 + cq;
            *(float2*)(O0 + col) =
                make_float2(o_acc[mi][ni][0] * inv0, o_acc[mi][ni][1] * inv0);
            *(float2*)(O1 + col) =
                make_float2(o_acc[mi][ni][2] * inv1, o_acc[mi][ni][3] * inv1);
        }
    }
}

// ===========================================================================
// Launch
// ===========================================================================
extern "C" void kernel_launch(void* const* d_in, const int* in_sizes, int n_in,
                              void* d_out, int out_size)
{
    const float* X     = (const float*)d_in[0];
    const int*   pos32 = (const int*)d_in[1];
    const float* Wq = (const float*)d_in[2];
    const float* Wk = (const float*)d_in[3];
    const float* Wv = (const float*)d_in[4];
    const float* Wo = (const float*)d_in[5];
    float* out = (float*)d_out;

    float *Qp, *Kp, *Vp, *Ap;
    cudaGetSymbolAddress((void**)&Qp, g_Q);
    cudaGetSymbolAddress((void**)&Kp, g_K);
    cudaGetSymbolAddress((void**)&Vp, g_V);
    cudaGetSymbolAddress((void**)&Ap, g_A);
    bf16 *Xh, *Xl, *Ahp, *Alp;
    bf16 *Wqh, *Wql, *Wkh, *Wkl, *Wvh, *Wvl, *Woh, *Wol;
    bf16 *Qbh, *Qbl, *Kbh, *Kbl, *Vth, *Vtl;
    cudaGetSymbolAddress((void**)&Xh, g_Xh);   cudaGetSymbolAddress((void**)&Xl, g_Xl);
    cudaGetSymbolAddress((void**)&Ahp, g_Ah);  cudaGetSymbolAddress((void**)&Alp, g_Al);
    cudaGetSymbolAddress((void**)&Wqh, g_Wqh); cudaGetSymbolAddress((void**)&Wql, g_Wql);
    cudaGetSymbolAddress((void**)&Wkh, g_Wkh); cudaGetSymbolAddress((void**)&Wkl, g_Wkl);
    cudaGetSymbolAddress((void**)&Wvh, g_Wvh); cudaGetSymbolAddress((void**)&Wvl, g_Wvl);
    cudaGetSymbolAddress((void**)&Woh, g_Woh); cudaGetSymbolAddress((void**)&Wol, g_Wol);
    cudaGetSymbolAddress((void**)&Qbh, g_Qbh); cudaGetSymbolAddress((void**)&Qbl, g_Qbl);
    cudaGetSymbolAddress((void**)&Kbh, g_Kbh); cudaGetSymbolAddress((void**)&Kbl, g_Kbl);
    cudaGetSymbolAddress((void**)&Vth, g_Vth); cudaGetSymbolAddress((void**)&Vtl, g_Vtl);

    cudaFuncSetAttribute(gemm_mma_kernel,
                         cudaFuncAttributeMaxDynamicSharedMemorySize, GEMM_SMEM);
    cudaFuncSetAttribute(attn_mma_kernel,
                         cudaFuncAttributeMaxDynamicSharedMemorySize, AT_SMEM);

    detect_pos_kernel<<<1, 1>>>(pos32);

    const int nX4 = TOKENS * HID / 4;
    split_kernel<<<(nX4 + 255) / 256, 256>>>(X, Xh, Xl, nX4);
    transpose_split_kernel<<<dim3(HID / 32, HID / 32), 256>>>(Wq, Wqh, Wql, HID, HID);
    transpose_split_kernel<<<dim3(KVDIM / 32, HID / 32), 256>>>(Wk, Wkh, Wkl, HID, KVDIM);
    transpose_split_kernel<<<dim3(KVDIM / 32, HID / 32), 256>>>(Wv, Wvh, Wvl, HID, KVDIM);
    transpose_split_kernel<<<dim3(HID / 32, HID / 32), 256>>>(Wo, Woh, Wol, HID, HID);

    gemm_mma_kernel<<<dim3(HID / 128, TOKENS / 128), 256, GEMM_SMEM>>>(
        Xh, Xl, Wqh, Wql, Qp, TOKENS, HID, HID);
    gemm_mma_kernel<<<dim3(KVDIM / 128, TOKENS / 128), 256, GEMM_SMEM>>>(
        Xh, Xl, Wkh, Wkl, Kp, TOKENS, KVDIM, HID);
    gemm_mma_kernel<<<dim3(KVDIM / 128, TOKENS / 128), 256, GEMM_SMEM>>>(
        Xh, Xl, Wvh, Wvl, Vp, TOKENS, KVDIM, HID);

    rope_split_kernel<<<TOKENS, 256>>>(Qp, Kp, pos32, Qbh, Qbl, Kbh, Kbl);
    transpose_split_v_kernel<<<dim3(S_ / 32, HD / 32, B_ * NKV), 256>>>(Vp, Vth, Vtl);

    attn_mma_kernel<<<dim3(S_ / 64, NH, B_), 256, AT_SMEM>>>(
        Qbh, Qbl, Kbh, Kbl, Vth, Vtl, Ap);

    split_kernel<<<(nX4 + 255) / 256, 256>>>(Ap, Ahp, Alp, nX4);
    gemm_mma_kernel<<<dim3(HID / 128, TOKENS / 128), 256, GEMM_SMEM>>>(
        Ahp, Alp, Woh, Wol, out, TOKENS, HID, HID);
}

// round 6
// speedup vs baseline: 3.3635x; 1.2826x over previous
#include <cuda_runtime.h>
#include <cuda_bf16.h>
#include <math.h>
#include <stdint.h>

// ---------------------------------------------------------------------------
// GroupedQueryAttention, GB300 (harness PTX target compute_103: no tcgen05).
// Round 6: FA2-style register-softmax attention (no S/P smem roundtrips,
// 128 q-rows/CTA) + 3-stage GEMM pipeline. Split-bf16 3-product everywhere.
// ---------------------------------------------------------------------------

#define B_ 2
#define S_ 2048
#define HID 4096
#define NH 32
#define NKV 8
#define HD 128
#define TOKENS (B_ * S_)
#define KVDIM (NKV * HD)

typedef __nv_bfloat16 bf16;

__device__ float g_Q[TOKENS * NH * HD];
__device__ float g_K[TOKENS * NKV * HD];
__device__ float g_V[TOKENS * NKV * HD];
__device__ float g_A[TOKENS * NH * HD];
__device__ int   g_pos_is64;

__device__ bf16 g_Xh[TOKENS * HID];
__device__ bf16 g_Xl[TOKENS * HID];
__device__ bf16 g_Ah[TOKENS * HID];
__device__ bf16 g_Al[TOKENS * HID];
__device__ bf16 g_Wqh[HID * HID];
__device__ bf16 g_Wql[HID * HID];
__device__ bf16 g_Wkh[KVDIM * HID];
__device__ bf16 g_Wkl[KVDIM * HID];
__device__ bf16 g_Wvh[KVDIM * HID];
__device__ bf16 g_Wvl[KVDIM * HID];
__device__ bf16 g_Woh[HID * HID];
__device__ bf16 g_Wol[HID * HID];

__device__ bf16 g_Qbh[TOKENS * NH * HD];
__device__ bf16 g_Qbl[TOKENS * NH * HD];
__device__ bf16 g_Kbh[TOKENS * NKV * HD];
__device__ bf16 g_Kbl[TOKENS * NKV * HD];
__device__ bf16 g_Vth[B_ * NKV * HD * S_];
__device__ bf16 g_Vtl[B_ * NKV * HD * S_];

// ===========================================================================
// Helpers
// ===========================================================================
__device__ __forceinline__ uint32_t smem_u32(const void* p) {
    uint32_t a;
    asm("{ .reg .u64 t; cvta.to.shared.u64 t, %1; cvt.u32.u64 %0, t; }"
        : "=r"(a) : "l"(p));
    return a;
}
__device__ __forceinline__ uint32_t swz(uint32_t off) {
    return off ^ ((off >> 3) & 0x70);
}

#define CP_ASYNC16(dst, src) \
    asm volatile("cp.async.cg.shared.global [%0], [%1], 16;" \
        :: "r"(dst), "l"(src) : "memory")
#define CP_COMMIT() asm volatile("cp.async.commit_group;" ::: "memory")
#define CP_WAIT(n)  asm volatile("cp.async.wait_group %0;" :: "n"(n) : "memory")

#define LDSM_X4(r0, r1, r2, r3, addr) \
    asm volatile("ldmatrix.sync.aligned.m8n8.x4.shared.b16 {%0,%1,%2,%3}, [%4];" \
        : "=r"(r0), "=r"(r1), "=r"(r2), "=r"(r3) : "r"(addr))

#define MMA_BF16(d, a, b0v, b1v) \
    asm volatile("mma.sync.aligned.m16n8k16.row.col.f32.bf16.bf16.f32 " \
        "{%0,%1,%2,%3}, {%4,%5,%6,%7}, {%8,%9}, {%0,%1,%2,%3};" \
        : "+f"((d)[0]), "+f"((d)[1]), "+f"((d)[2]), "+f"((d)[3]) \
        : "r"((a)[0]), "r"((a)[1]), "r"((a)[2]), "r"((a)[3]), \
          "r"(b0v), "r"(b1v))

// ===========================================================================
// position_ids dtype probe
// ===========================================================================
__global__ void detect_pos_kernel(const int* __restrict__ p)
{
    if (threadIdx.x == 0 && blockIdx.x == 0)
        g_pos_is64 = (p[1] == 0 && p[3] == 0 && p[5] == 0 && p[7] == 0) ? 1 : 0;
}

// ===========================================================================
// Split fp32 -> (bf16 hi, bf16 lo)
// ===========================================================================
__global__ __launch_bounds__(256) void split_kernel(
    const float* __restrict__ x, bf16* __restrict__ h,
    bf16* __restrict__ l, int n4)
{
    int i = blockIdx.x * 256 + threadIdx.x;
    if (i >= n4) return;
    float4 v = *(const float4*)(x + (size_t)i * 4);
    bf16 h0 = __float2bfloat16_rn(v.x);
    bf16 h1 = __float2bfloat16_rn(v.y);
    bf16 h2 = __float2bfloat16_rn(v.z);
    bf16 h3 = __float2bfloat16_rn(v.w);
    bf16 l0 = __float2bfloat16_rn(v.x - __bfloat162float(h0));
    bf16 l1 = __float2bfloat16_rn(v.y - __bfloat162float(h1));
    bf16 l2 = __float2bfloat16_rn(v.z - __bfloat162float(h2));
    bf16 l3 = __float2bfloat16_rn(v.w - __bfloat162float(h3));
    __nv_bfloat162* H = (__nv_bfloat162*)(h + (size_t)i * 4);
    __nv_bfloat162* L = (__nv_bfloat162*)(l + (size_t)i * 4);
    H[0] = __nv_bfloat162(h0, h1); H[1] = __nv_bfloat162(h2, h3);
    L[0] = __nv_bfloat162(l0, l1); L[1] = __nv_bfloat162(l2, l3);
}

// ===========================================================================
// Transpose + split
// ===========================================================================
__global__ __launch_bounds__(256) void transpose_split_kernel(
    const float* __restrict__ W, bf16* __restrict__ Th,
    bf16* __restrict__ Tl, int Kd, int Nd)
{
    __shared__ float t[32][33];
    const int n0 = blockIdx.x * 32, k0 = blockIdx.y * 32;
    const int tx = threadIdx.x & 31, ty = threadIdx.x >> 5;
    #pragma unroll
    for (int r = 0; r < 4; r++)
        t[ty + r * 8][tx] = W[(size_t)(k0 + ty + r * 8) * Nd + n0 + tx];
    __syncthreads();
    #pragma unroll
    for (int r = 0; r < 4; r++) {
        float v = t[tx][ty + r * 8];
        bf16 h = __float2bfloat16_rn(v);
        bf16 l = __float2bfloat16_rn(v - __bfloat162float(h));
        size_t o = (size_t)(n0 + ty + r * 8) * Kd + k0 + tx;
        Th[o] = h; Tl[o] = l;
    }
}

// ===========================================================================
// V transpose + split: [b][s][kvh][d] -> [b][kvh][d][s]
// ===========================================================================
__global__ __launch_bounds__(256) void transpose_split_v_kernel(
    const float* __restrict__ V, bf16* __restrict__ Vth, bf16* __restrict__ Vtl)
{
    __shared__ float t[32][33];
    const int s0 = blockIdx.x * 32, d0 = blockIdx.y * 32;
    const int bk = blockIdx.z;
    const int b = bk / NKV, kvh = bk % NKV;
    const int tx = threadIdx.x & 31, ty = threadIdx.x >> 5;
    #pragma unroll
    for (int r = 0; r < 4; r++) {
        int s = s0 + ty + r * 8;
        t[ty + r * 8][tx] = V[((size_t)(b * S_ + s) * NKV + kvh) * HD + d0 + tx];
    }
    __syncthreads();
    #pragma unroll
    for (int r = 0; r < 4; r++) {
        int d = d0 + ty + r * 8;
        float v = t[tx][ty + r * 8];
        bf16 h = __float2bfloat16_rn(v);
        bf16 l = __float2bfloat16_rn(v - __bfloat162float(h));
        size_t o = ((size_t)bk * HD + d) * S_ + s0 + tx;
        Vth[o] = h; Vtl[o] = l;
    }
}

// ===========================================================================
// mma.sync split-bf16 GEMM, 3-stage cp.async pipeline
// ===========================================================================
#define TK 64
#define TILE_BYTES (128 * 128)
#define STAGE_BYTES (4 * TILE_BYTES)
#define GEMM_SMEM (3 * STAGE_BYTES)

__global__ __launch_bounds__(256, 1) void gemm_mma_kernel(
    const bf16* __restrict__ Ah, const bf16* __restrict__ Al,
    const bf16* __restrict__ Bh, const bf16* __restrict__ Bl,
    float* __restrict__ C, int M, int N, int K)
{
    extern __shared__ char smc[];
    const uint32_t sbase = smem_u32(smc);
    const int tid = threadIdx.x;
    const int wid = tid >> 5, lane = tid & 31;
    const int wm = wid & 1, wn = wid >> 1;
    const int m0 = blockIdx.y * 128;
    const int n0 = blockIdx.x * 128;

    const int nch = K / TK;

    auto load_chunk = [&](int kc, int s) {
        const uint32_t base = sbase + (uint32_t)s * STAGE_BYTES;
        const bf16* srcs[4] = {Ah, Al, Bh, Bl};
        const int row0s[4] = {m0, m0, n0, n0};
        #pragma unroll
        for (int t = 0; t < 4; t++) {
            const bf16* src = srcs[t] + (size_t)kc * TK;
            const int row0 = row0s[t];
            const uint32_t dst = base + (uint32_t)t * TILE_BYTES;
            #pragma unroll
            for (int g4 = 0; g4 < 4; g4++) {
                int g = tid + g4 * 256;
                int r = g >> 3, c = g & 7;
                const bf16* gp = src + (size_t)(row0 + r) * K + c * 8;
                uint32_t off = swz((uint32_t)((r << 7) + (c << 4)));
                CP_ASYNC16(dst + off, gp);
            }
        }
    };

    float acc[4][4][4];
    #pragma unroll
    for (int mi = 0; mi < 4; mi++)
        #pragma unroll
        for (int ni = 0; ni < 4; ni++)
            #pragma unroll
            for (int r = 0; r < 4; r++) acc[mi][ni][r] = 0.f;

    const uint32_t lrow = (uint32_t)(lane & 15);
    const uint32_t lcol = (uint32_t)((lane >> 4) << 4);

    load_chunk(0, 0);
    CP_COMMIT();
    if (nch > 1) { load_chunk(1, 1); CP_COMMIT(); }

    for (int i = 0; i < nch; i++) {
        if (i + 2 < nch) {
            load_chunk(i + 2, (i + 2) % 3);
            CP_COMMIT();
            CP_WAIT(2);
        } else if (i + 1 < nch) {
            CP_WAIT(1);
        } else {
            CP_WAIT(0);
        }
        __syncthreads();

        const uint32_t st = sbase + (uint32_t)(i % 3) * STAGE_BYTES;
        const uint32_t tAh = st;
        const uint32_t tAl = st + TILE_BYTES;
        const uint32_t tBh = st + 2 * TILE_BYTES;
        const uint32_t tBl = st + 3 * TILE_BYTES;

        #pragma unroll
        for (int ks = 0; ks < 4; ks++) {
            const uint32_t kb = (uint32_t)(ks << 5) + lcol;
            uint32_t fAh[4][4], fAl[4][4], fBh[2][4], fBl[2][4];
            #pragma unroll
            for (int mi = 0; mi < 4; mi++) {
                uint32_t ro = ((uint32_t)(wm * 64 + mi * 16) + lrow) << 7;
                uint32_t ad = swz(ro + kb);
                LDSM_X4(fAh[mi][0], fAh[mi][1], fAh[mi][2], fAh[mi][3], tAh + ad);
                LDSM_X4(fAl[mi][0], fAl[mi][1], fAl[mi][2], fAl[mi][3], tAl + ad);
            }
            #pragma unroll
            for (int j = 0; j < 2; j++) {
                uint32_t ro = ((uint32_t)(wn * 32 + j * 16) + lrow) << 7;
                uint32_t ad = swz(ro + kb);
                LDSM_X4(fBh[j][0], fBh[j][1], fBh[j][2], fBh[j][3], tBh + ad);
                LDSM_X4(fBl[j][0], fBl[j][1], fBl[j][2], fBl[j][3], tBl + ad);
            }
            #pragma unroll
            for (int mi = 0; mi < 4; mi++) {
                #pragma unroll
                for (int ni = 0; ni < 4; ni++) {
                    const int j = ni >> 1, p = ni & 1;
                    MMA_BF16(acc[mi][ni], fAh[mi], fBh[j][p], fBh[j][2 + p]);
                    MMA_BF16(acc[mi][ni], fAh[mi], fBl[j][p], fBl[j][2 + p]);
                    MMA_BF16(acc[mi][ni], fAl[mi], fBh[j][p], fBh[j][2 + p]);
                }
            }
        }
        __syncthreads();
    }

    float* Cw = C + (size_t)(m0 + wm * 64) * N + n0 + wn * 32;
    const int rq = lane >> 2, cq = (lane & 3) << 1;
    #pragma unroll
    for (int mi = 0; mi < 4; mi++) {
        #pragma unroll
        for (int ni = 0; ni < 4; ni++) {
            float2 v0 = make_float2(acc[mi][ni][0], acc[mi][ni][1]);
            float2 v1 = make_float2(acc[mi][ni][2], acc[mi][ni][3]);
            *(float2*)(Cw + (size_t)(mi * 16 + rq) * N + ni * 8 + cq)     = v0;
            *(float2*)(Cw + (size_t)(mi * 16 + rq + 8) * N + ni * 8 + cq) = v1;
        }
    }
}

// ===========================================================================
// RoPE + split
// ===========================================================================
__global__ __launch_bounds__(256) void rope_split_kernel(
    const float* __restrict__ Q, const float* __restrict__ K,
    const int* __restrict__ pos32,
    bf16* __restrict__ Qbh, bf16* __restrict__ Qbl,
    bf16* __restrict__ Kbh, bf16* __restrict__ Kbl)
{
    const int token = blockIdx.x;
    const int pidx = g_pos_is64 ? (token << 1) : token;
    const float p = (float)pos32[pidx];
    const int tid = threadIdx.x;

    const float* Qb = Q + (size_t)token * (NH * HD);
    bf16* Qh = Qbh + (size_t)token * (NH * HD);
    bf16* Ql = Qbl + (size_t)token * (NH * HD);
    for (int idx = tid; idx < NH * 64; idx += 256) {
        int h = idx >> 6, i = idx & 63;
        float inv = powf(10000.0f, -(float)(2 * i) * (1.0f / 128.0f));
        float sv, cv;
        sincosf(p * inv, &sv, &cv);
        float x1 = Qb[h * HD + i];
        float x2 = Qb[h * HD + i + 64];
        float y1 = x1 * cv - x2 * sv;
        float y2 = x2 * cv + x1 * sv;
        bf16 h1 = __float2bfloat16_rn(y1);
        bf16 h2 = __float2bfloat16_rn(y2);
        Qh[h * HD + i]      = h1;
        Qh[h * HD + i + 64] = h2;
        Ql[h * HD + i]      = __float2bfloat16_rn(y1 - __bfloat162float(h1));
        Ql[h * HD + i + 64] = __float2bfloat16_rn(y2 - __bfloat162float(h2));
    }

    const float* Kb = K + (size_t)token * (NKV * HD);
    bf16* Kh = Kbh + (size_t)token * (NKV * HD);
    bf16* Kl = Kbl + (size_t)token * (NKV * HD);
    for (int idx = tid; idx < NKV * 64; idx += 256) {
        int h = idx >> 6, i = idx & 63;
        float inv = powf(10000.0f, -(float)(2 * i) * (1.0f / 128.0f));
        float sv, cv;
        sincosf(p * inv, &sv, &cv);
        float x1 = Kb[h * HD + i];
        float x2 = Kb[h * HD + i + 64];
        float y1 = x1 * cv - x2 * sv;
        float y2 = x2 * cv + x1 * sv;
        bf16 h1 = __float2bfloat16_rn(y1);
        bf16 h2 = __float2bfloat16_rn(y2);
        Kh[h * HD + i]      = h1;
        Kh[h * HD + i + 64] = h2;
        Kl[h * HD + i]      = __float2bfloat16_rn(y1 - __bfloat162float(h1));
        Kl[h * HD + i + 64] = __float2bfloat16_rn(y2 - __bfloat162float(h2));
    }
}

// ===========================================================================
// FA2-style mma.sync flash attention: 128 q-rows/CTA, register softmax.
// 8 warps, each owns 16 q-rows x full N. smem: Q 64K | K 2x32K | V 2x32K.
// ===========================================================================
#define FA_Q_OFF  0
#define FA_K_OFF  65536
#define FA_V_OFF  131072
#define FA_SMEM   196608

__global__ __launch_bounds__(256, 1) void attn_fa2_kernel(
    const bf16* __restrict__ Qbh, const bf16* __restrict__ Qbl,
    const bf16* __restrict__ Kbh, const bf16* __restrict__ Kbl,
    const bf16* __restrict__ Vth, const bf16* __restrict__ Vtl,
    float* __restrict__ O)
{
    extern __shared__ char smc[];
    const uint32_t sb = smem_u32(smc);
    const int qt = blockIdx.x;          // 0..15 (128-row q tiles)
    const int h  = blockIdx.y;
    const int b  = blockIdx.z;
    const int kvh = h >> 2;
    const int bk = b * NKV + kvh;

    const int tid = threadIdx.x;
    const int wid = tid >> 5, lane = tid & 31;
    const uint32_t lrow = (uint32_t)(lane & 15);
    const uint32_t lcol = (uint32_t)((lane >> 4) << 4);
    const int rq = lane >> 2, cq = (lane & 3) << 1;

    const float scale = 0.08838834764831845f;  // 1/sqrt(128)

    // ---- Q load (once): 4096 granules, chunks (hl*2+c) of 16KB ----
    {
        const bf16* Qsrc[2] = {Qbh, Qbl};
        #pragma unroll
        for (int g4 = 0; g4 < 16; g4++) {
            int g = tid + g4 * 256;
            int hl = g >> 11, rem = g & 2047;
            int c = rem >> 10, r = (rem >> 3) & 127, gr = rem & 7;
            const bf16* gp = Qsrc[hl] +
                ((size_t)((b * S_ + qt * 128 + r) * NH + h) * HD + c * 64 + gr * 8);
            uint32_t dst = sb + FA_Q_OFF + (uint32_t)(hl * 2 + c) * 16384 +
                           swz((uint32_t)((r << 7) + (gr << 4)));
            CP_ASYNC16(dst, gp);
        }
    }

    // ---- K/V tile loader (64 keys) ----
    auto load_kv = [&](int kt, int s) {
        const bf16* Ks[2] = {Kbh, Kbl};
        #pragma unroll
        for (int g4 = 0; g4 < 8; g4++) {
            int g = tid + g4 * 256;
            int hl = g >> 10, rem = g & 1023;
            int c = rem >> 9, r = (rem >> 3) & 63, gr = rem & 7;
            const bf16* gp = Ks[hl] +
                ((size_t)((b * S_ + kt * 64 + r) * NKV + kvh) * HD + c * 64 + gr * 8);
            uint32_t dst = sb + FA_K_OFF + (uint32_t)s * 32768 +
                           (uint32_t)(hl * 2 + c) * 8192 +
                           swz((uint32_t)((r << 7) + (gr << 4)));
            CP_ASYNC16(dst, gp);
        }
        const bf16* Vs[2] = {Vth, Vtl};
        #pragma unroll
        for (int g4 = 0; g4 < 8; g4++) {
            int g = tid + g4 * 256;
            int hl = g >> 10, rem = g & 1023;
            int d = rem >> 3, gr = rem & 7;
            const bf16* gp = Vs[hl] +
                ((size_t)bk * HD + d) * S_ + kt * 64 + gr * 8;
            uint32_t dst = sb + FA_V_OFF + (uint32_t)s * 32768 +
                           (uint32_t)hl * 16384 +
                           swz((uint32_t)((d << 7) + (gr << 4)));
            CP_ASYNC16(dst, gp);
        }
    };

    load_kv(0, 0);
    CP_COMMIT();

    float m_[2] = {-INFINITY, -INFINITY};
    float l_[2] = {0.f, 0.f};
    float o_acc[16][4];
    #pragma unroll
    for (int t = 0; t < 16; t++)
        #pragma unroll
        for (int r = 0; r < 4; r++) o_acc[t][r] = 0.f;

    for (int kt = 0; kt < S_ / 64; kt++) {
        const int st = kt & 1;
        if (kt + 1 < S_ / 64) {
            load_kv(kt + 1, st ^ 1);
            CP_COMMIT();
            CP_WAIT(1);
        } else {
            CP_WAIT(0);
        }
        __syncthreads();

        // ---- S = Q K^T (3 products), rows wid*16..+16, cols 0..63 ----
        float s_acc[8][4];
        #pragma unroll
        for (int t = 0; t < 8; t++)
            #pragma unroll
            for (int r = 0; r < 4; r++) s_acc[t][r] = 0.f;

        const uint32_t Kb0 = sb + FA_K_OFF + (uint32_t)st * 32768;
        #pragma unroll
        for (int c = 0; c < 2; c++) {
            const uint32_t qch = sb + FA_Q_OFF + (uint32_t)c * 16384;
            const uint32_t qcl = sb + FA_Q_OFF + (uint32_t)(2 + c) * 16384;
            const uint32_t kch = Kb0 + (uint32_t)c * 8192;
            const uint32_t kcl = Kb0 + (uint32_t)(2 + c) * 8192;
            #pragma unroll
            for (int ks = 0; ks < 4; ks++) {
                const uint32_t kb = (uint32_t)(ks << 5) + lcol;
                uint32_t fQh[4], fQl[4];
                uint32_t ad = swz((((uint32_t)(wid * 16) + lrow) << 7) + kb);
                LDSM_X4(fQh[0], fQh[1], fQh[2], fQh[3], qch + ad);
                LDSM_X4(fQl[0], fQl[1], fQl[2], fQl[3], qcl + ad);
                #pragma unroll
                for (int nt2 = 0; nt2 < 4; nt2++) {
                    uint32_t fKh[4], fKl[4];
                    uint32_t kad = swz((((uint32_t)(nt2 * 16) + lrow) << 7) + kb);
                    LDSM_X4(fKh[0], fKh[1], fKh[2], fKh[3], kch + kad);
                    LDSM_X4(fKl[0], fKl[1], fKl[2], fKl[3], kcl + kad);
                    const int t0 = nt2 * 2;
                    MMA_BF16(s_acc[t0],     fQh, fKh[0], fKh[2]);
                    MMA_BF16(s_acc[t0 + 1], fQh, fKh[1], fKh[3]);
                    MMA_BF16(s_acc[t0],     fQh, fKl[0], fKl[2]);
                    MMA_BF16(s_acc[t0 + 1], fQh, fKl[1], fKl[3]);
                    MMA_BF16(s_acc[t0],     fQl, fKh[0], fKh[2]);
                    MMA_BF16(s_acc[t0 + 1], fQl, fKh[1], fKh[3]);
                }
            }
        }

        // ---- register online softmax (rows wid*16+rq, +8) ----
        float mx0 = -INFINITY, mx1 = -INFINITY;
        #pragma unroll
        for (int t = 0; t < 8; t++) {
            #pragma unroll
            for (int r = 0; r < 4; r++) s_acc[t][r] *= scale;
            mx0 = fmaxf(mx0, fmaxf(s_acc[t][0], s_acc[t][1]));
            mx1 = fmaxf(mx1, fmaxf(s_acc[t][2], s_acc[t][3]));
        }
        mx0 = fmaxf(mx0, __shfl_xor_sync(0xffffffffu, mx0, 1));
        mx0 = fmaxf(mx0, __shfl_xor_sync(0xffffffffu, mx0, 2));
        mx1 = fmaxf(mx1, __shfl_xor_sync(0xffffffffu, mx1, 1));
        mx1 = fmaxf(mx1, __shfl_xor_sync(0xffffffffu, mx1, 2));

        const float mn0 = fmaxf(m_[0], mx0);
        const float mn1 = fmaxf(m_[1], mx1);
        const float sc0 = __expf(m_[0] - mn0);
        const float sc1 = __expf(m_[1] - mn1);

        // P = exp(S - m), pack hi (fp32 truncation) + lo fragments in-register
        uint32_t aPh[4][4], aPl[4][4];
        float ls0 = 0.f, ls1 = 0.f;
        #pragma unroll
        for (int t = 0; t < 8; t++) {
            float p0 = __expf(s_acc[t][0] - mn0);
            float p1 = __expf(s_acc[t][1] - mn0);
            float p2 = __expf(s_acc[t][2] - mn1);
            float p3 = __expf(s_acc[t][3] - mn1);
            ls0 += p0 + p1;
            ls1 += p2 + p3;
            uint32_t u0 = __float_as_uint(p0), u1 = __float_as_uint(p1);
            uint32_t u2 = __float_as_uint(p2), u3 = __float_as_uint(p3);
            uint32_t hi01 = (u0 >> 16) | (u1 & 0xFFFF0000u);
            uint32_t hi23 = (u2 >> 16) | (u3 & 0xFFFF0000u);
            float r0 = p0 - __uint_as_float(u0 & 0xFFFF0000u);
            float r1 = p1 - __uint_as_float(u1 & 0xFFFF0000u);
            float r2 = p2 - __uint_as_float(u2 & 0xFFFF0000u);
            float r3 = p3 - __uint_as_float(u3 & 0xFFFF0000u);
            __nv_bfloat162 lo01 = __float22bfloat162_rn(make_float2(r0, r1));
            __nv_bfloat162 lo23 = __float22bfloat162_rn(make_float2(r2, r3));
            const int kk = t >> 1;
            if ((t & 1) == 0) {
                aPh[kk][0] = hi01; aPh[kk][1] = hi23;
                aPl[kk][0] = *(uint32_t*)&lo01; aPl[kk][1] = *(uint32_t*)&lo23;
            } else {
                aPh[kk][2] = hi01; aPh[kk][3] = hi23;
                aPl[kk][2] = *(uint32_t*)&lo01; aPl[kk][3] = *(uint32_t*)&lo23;
            }
        }
        ls0 += __shfl_xor_sync(0xffffffffu, ls0, 1);
        ls0 += __shfl_xor_sync(0xffffffffu, ls0, 2);
        ls1 += __shfl_xor_sync(0xffffffffu, ls1, 1);
        ls1 += __shfl_xor_sync(0xffffffffu, ls1, 2);
        l_[0] = l_[0] * sc0 + ls0;
        l_[1] = l_[1] * sc1 + ls1;
        m_[0] = mn0;
        m_[1] = mn1;

        // rescale O
        #pragma unroll
        for (int t = 0; t < 16; t++) {
            o_acc[t][0] *= sc0; o_acc[t][1] *= sc0;
            o_acc[t][2] *= sc1; o_acc[t][3] *= sc1;
        }

        // ---- O += P V (3 products) ----
        const uint32_t Vbh = sb + FA_V_OFF + (uint32_t)st * 32768;
        const uint32_t Vbl = Vbh + 16384;
        #pragma unroll
        for (int kk = 0; kk < 4; kk++) {
            const uint32_t kb = (uint32_t)(kk << 5) + lcol;
            #pragma unroll
            for (int nt2 = 0; nt2 < 8; nt2++) {
                uint32_t fVh[4], fVl[4];
                uint32_t ad = swz((((uint32_t)(nt2 * 16) + lrow) << 7) + kb);
                LDSM_X4(fVh[0], fVh[1], fVh[2], fVh[3], Vbh + ad);
                LDSM_X4(fVl[0], fVl[1], fVl[2], fVl[3], Vbl + ad);
                const int t0 = nt2 * 2;
                MMA_BF16(o_acc[t0],     aPh[kk], fVh[0], fVh[2]);
                MMA_BF16(o_acc[t0 + 1], aPh[kk], fVh[1], fVh[3]);
                MMA_BF16(o_acc[t0],     aPh[kk], fVl[0], fVl[2]);
                MMA_BF16(o_acc[t0 + 1], aPh[kk], fVl[1], fVl[3]);
                MMA_BF16(o_acc[t0],     aPl[kk], fVh[0], fVh[2]);
                MMA_BF16(o_acc[t0 + 1], aPl[kk], fVh[1], fVh[3]);
            }
        }
        __syncthreads();
    }

    // ---- epilogue ----
    const float inv0 = 1.0f / l_[0];
    const float inv1 = 1.0f / l_[1];
    const int row0 = qt * 128 + wid * 16 + rq;
    float* O0 = O + ((size_t)(b * S_ + row0) * NH + h) * HD;
    float* O1 = O + ((size_t)(b * S_ + row0 + 8) * NH + h) * HD;
    #pragma unroll
    for (int t = 0; t < 16; t++) {
        const int col = t * 8 + cq;
        *(float2*)(O0 + col) = make_float2(o_acc[t][0] * inv0, o_acc[t][1] * inv0);
        *(float2*)(O1 + col) = make_float2(o_acc[t][2] * inv1, o_acc[t][3] * inv1);
    }
}

// ===========================================================================
// Launch
// ===========================================================================
extern "C" void kernel_launch(void* const* d_in, const int* in_sizes, int n_in,
                              void* d_out, int out_size)
{
    const float* X     = (const float*)d_in[0];
    const int*   pos32 = (const int*)d_in[1];
    const float* Wq = (const float*)d_in[2];
    const float* Wk = (const float*)d_in[3];
    const float* Wv = (const float*)d_in[4];
    const float* Wo = (const float*)d_in[5];
    float* out = (float*)d_out;

    float *Qp, *Kp, *Vp, *Ap;
    cudaGetSymbolAddress((void**)&Qp, g_Q);
    cudaGetSymbolAddress((void**)&Kp, g_K);
    cudaGetSymbolAddress((void**)&Vp, g_V);
    cudaGetSymbolAddress((void**)&Ap, g_A);
    bf16 *Xh, *Xl, *Ahp, *Alp;
    bf16 *Wqh, *Wql, *Wkh, *Wkl, *Wvh, *Wvl, *Woh, *Wol;
    bf16 *Qbh, *Qbl, *Kbh, *Kbl, *Vth, *Vtl;
    cudaGetSymbolAddress((void**)&Xh, g_Xh);   cudaGetSymbolAddress((void**)&Xl, g_Xl);
    cudaGetSymbolAddress((void**)&Ahp, g_Ah);  cudaGetSymbolAddress((void**)&Alp, g_Al);
    cudaGetSymbolAddress((void**)&Wqh, g_Wqh); cudaGetSymbolAddress((void**)&Wql, g_Wql);
    cudaGetSymbolAddress((void**)&Wkh, g_Wkh); cudaGetSymbolAddress((void**)&Wkl, g_Wkl);
    cudaGetSymbolAddress((void**)&Wvh, g_Wvh); cudaGetSymbolAddress((void**)&Wvl, g_Wvl);
    cudaGetSymbolAddress((void**)&Woh, g_Woh); cudaGetSymbolAddress((void**)&Wol, g_Wol);
    cudaGetSymbolAddress((void**)&Qbh, g_Qbh); cudaGetSymbolAddress((void**)&Qbl, g_Qbl);
    cudaGetSymbolAddress((void**)&Kbh, g_Kbh); cudaGetSymbolAddress((void**)&Kbl, g_Kbl);
    cudaGetSymbolAddress((void**)&Vth, g_Vth); cudaGetSymbolAddress((void**)&Vtl, g_Vtl);

    cudaFuncSetAttribute(gemm_mma_kernel,
                         cudaFuncAttributeMaxDynamicSharedMemorySize, GEMM_SMEM);
    cudaFuncSetAttribute(attn_fa2_kernel,
                         cudaFuncAttributeMaxDynamicSharedMemorySize, FA_SMEM);

    detect_pos_kernel<<<1, 1>>>(pos32);

    const int nX4 = TOKENS * HID / 4;
    split_kernel<<<(nX4 + 255) / 256, 256>>>(X, Xh, Xl, nX4);
    transpose_split_kernel<<<dim3(HID / 32, HID / 32), 256>>>(Wq, Wqh, Wql, HID, HID);
    transpose_split_kernel<<<dim3(KVDIM / 32, HID / 32), 256>>>(Wk, Wkh, Wkl, HID, KVDIM);
    transpose_split_kernel<<<dim3(KVDIM / 32, HID / 32), 256>>>(Wv, Wvh, Wvl, HID, KVDIM);
    transpose_split_kernel<<<dim3(HID / 32, HID / 32), 256>>>(Wo, Woh, Wol, HID, HID);

    gemm_mma_kernel<<<dim3(HID / 128, TOKENS / 128), 256, GEMM_SMEM>>>(
        Xh, Xl, Wqh, Wql, Qp, TOKENS, HID, HID);
    gemm_mma_kernel<<<dim3(KVDIM / 128, TOKENS / 128), 256, GEMM_SMEM>>>(
        Xh, Xl, Wkh, Wkl, Kp, TOKENS, KVDIM, HID);
    gemm_mma_kernel<<<dim3(KVDIM / 128, TOKENS / 128), 256, GEMM_SMEM>>>(
        Xh, Xl, Wvh, Wvl, Vp, TOKENS, KVDIM, HID);

    rope_split_kernel<<<TOKENS, 256>>>(Qp, Kp, pos32, Qbh, Qbl, Kbh, Kbl);
    transpose_split_v_kernel<<<dim3(S_ / 32, HD / 32, B_ * NKV), 256>>>(Vp, Vth, Vtl);

    attn_fa2_kernel<<<dim3(S_ / 128, NH, B_), 256, FA_SMEM>>>(
        Qbh, Qbl, Kbh, Kbl, Vth, Vtl, Ap);

    split_kernel<<<(nX4 + 255) / 256, 256>>>(Ap, Ahp, Alp, nX4);
    gemm_mma_kernel<<<dim3(HID / 128, TOKENS / 128), 256, GEMM_SMEM>>>(
        Ahp, Alp, Woh, Wol, out, TOKENS, HID, HID);
}